// round 2
// baseline (speedup 1.0000x reference)
#include <cuda_runtime.h>
#include <cuda_bf16.h>
#include <cstdint>

// Problem constants
#define NB   2
#define C_   256
#define CI_  128
#define NN   65536            // D*H*W = 16*64*64
#define CK   2048             // k-chunk per syrk block
#define KT   32               // k-tile in smem

// ---------------- scratch (static device globals; no allocation) ----------------
__device__ float d_S[NB][C_][C_];      // X X^T per batch
__device__ float d_s[NB][C_];          // row sums
__device__ float d_u[NB][CI_];         // phi_w @ s
__device__ float d_v[NB][CI_];         // g_w @ s
__device__ float d_T1[NB][CI_][C_];    // phi_w @ S
__device__ float d_kv[NB][CI_][CI_];
__device__ float d_M[NB][C_][CI_];     // W_w kv^T / N
__device__ float d_A[NB][C_][C_];      // M @ theta_w
__device__ float d_b2[NB][C_];         // M @ theta_b + W_b

// ---------------- zero the accumulated buffers (S is atomicAdd target) ----------
__global__ void zero_kernel() {
    int idx = blockIdx.x * blockDim.x + threadIdx.x;
    float* p = &d_S[0][0][0];
    if (idx < NB * C_ * C_) p[idx] = 0.0f;
}

// ---------------- row sums: s[b][c] = sum_n x[b][c][n] ---------------------------
__global__ void rowsum_kernel(const float* __restrict__ x) {
    int b = blockIdx.y, c = blockIdx.x;
    const float4* p = (const float4*)(x + (size_t)(b * C_ + c) * NN);
    float acc = 0.0f;
    for (int i = threadIdx.x; i < NN / 4; i += 256) {
        float4 v = p[i];
        acc += v.x + v.y + v.z + v.w;
    }
    __shared__ float red[256];
    red[threadIdx.x] = acc;
    __syncthreads();
    for (int s = 128; s > 0; s >>= 1) {
        if (threadIdx.x < s) red[threadIdx.x] += red[threadIdx.x + s];
        __syncthreads();
    }
    if (threadIdx.x == 0) d_s[b][c] = red[0];
}

// ---------------- syrk: S[b] += X_b[128-quad rows] * X_b[128-quad rows]^T --------
// grid (NN/CK, 4, NB); block 256 (16x16); each thread an 8x8 micro-tile.
__global__ __launch_bounds__(256, 2) void syrk_kernel(const float* __restrict__ x) {
    int b  = blockIdx.z;
    int qm = blockIdx.y >> 1, qn = blockIdx.y & 1;
    int k0 = blockIdx.x * CK;
    __shared__ float As[KT][132];
    __shared__ float Bs[KT][132];
    int tid = threadIdx.x;
    int ty = tid >> 4, tx = tid & 15;
    float acc[8][8] = {};
    const float* xb = x + (size_t)b * C_ * NN;

    for (int kk = 0; kk < CK; kk += KT) {
#pragma unroll
        for (int l = 0; l < 4; l++) {
            int lin = tid + l * 256;           // float4 index over [128 rows][8 f4]
            int row = lin >> 3, c4 = lin & 7;
            float4 va = *(const float4*)(xb + (size_t)(qm * 128 + row) * NN + (k0 + kk + c4 * 4));
            As[c4 * 4 + 0][row] = va.x; As[c4 * 4 + 1][row] = va.y;
            As[c4 * 4 + 2][row] = va.z; As[c4 * 4 + 3][row] = va.w;
            float4 vb = *(const float4*)(xb + (size_t)(qn * 128 + row) * NN + (k0 + kk + c4 * 4));
            Bs[c4 * 4 + 0][row] = vb.x; Bs[c4 * 4 + 1][row] = vb.y;
            Bs[c4 * 4 + 2][row] = vb.z; Bs[c4 * 4 + 3][row] = vb.w;
        }
        __syncthreads();
#pragma unroll
        for (int k = 0; k < KT; k++) {
            float a[8], bb[8];
            *(float4*)(a)      = *(const float4*)&As[k][ty * 8];
            *(float4*)(a + 4)  = *(const float4*)&As[k][ty * 8 + 4];
            *(float4*)(bb)     = *(const float4*)&Bs[k][tx * 8];
            *(float4*)(bb + 4) = *(const float4*)&Bs[k][tx * 8 + 4];
#pragma unroll
            for (int i = 0; i < 8; i++)
#pragma unroll
                for (int j = 0; j < 8; j++) acc[i][j] += a[i] * bb[j];
        }
        __syncthreads();
    }
#pragma unroll
    for (int i = 0; i < 8; i++)
#pragma unroll
        for (int j = 0; j < 8; j++)
            atomicAdd(&d_S[b][qm * 128 + ty * 8 + i][qn * 128 + tx * 8 + j], acc[i][j]);
}

// ---------------- small chain ----------------------------------------------------
__global__ void uv_kernel(const float* __restrict__ phi_w, const float* __restrict__ g_w) {
    int b = blockIdx.y, i = threadIdx.x;
    float su = 0.0f, sv = 0.0f;
    for (int c = 0; c < C_; c++) {
        float sc = d_s[b][c];
        su += phi_w[i * C_ + c] * sc;
        sv += g_w[i * C_ + c] * sc;
    }
    d_u[b][i] = su;
    d_v[b][i] = sv;
}

// T1[b][i][c2] = sum_c phi_w[i][c] * S[b][c][c2];  block = one row i, threads = c2
__global__ void t1_kernel(const float* __restrict__ phi_w) {
    int b = blockIdx.y, i = blockIdx.x, c2 = threadIdx.x;
    float acc = 0.0f;
    for (int c = 0; c < C_; c++) acc += phi_w[i * C_ + c] * d_S[b][c][c2];
    d_T1[b][i][c2] = acc;
}

__global__ void kv_kernel(const float* __restrict__ g_w, const float* __restrict__ g_b,
                          const float* __restrict__ phi_b) {
    int b = blockIdx.y, i = blockIdx.x, j = threadIdx.x;
    float acc = 0.0f;
    for (int d = 0; d < C_; d++) acc += d_T1[b][i][d] * g_w[j * C_ + d];
    acc += d_u[b][i] * g_b[j] + phi_b[i] * d_v[b][j] + (float)NN * phi_b[i] * g_b[j];
    d_kv[b][i][j] = acc;
}

__global__ void m_kernel(const float* __restrict__ W_w) {
    int b = blockIdx.y, c = blockIdx.x, i = threadIdx.x;
    float acc = 0.0f;
    for (int j = 0; j < CI_; j++) acc += W_w[c * CI_ + j] * d_kv[b][i][j];
    d_M[b][c][i] = acc * (1.0f / (float)NN);
}

__global__ void a_kernel(const float* __restrict__ theta_w, const float* __restrict__ theta_b,
                         const float* __restrict__ W_b) {
    int b = blockIdx.y, c = blockIdx.x, dd = threadIdx.x;
    float acc = 0.0f;
    for (int i = 0; i < CI_; i++) acc += d_M[b][c][i] * theta_w[i * C_ + dd];
    d_A[b][c][dd] = acc;
    if (dd == 0) {
        float bb = W_b[c];
        for (int i = 0; i < CI_; i++) bb += d_M[b][c][i] * theta_b[i];
        d_b2[b][c] = bb;
    }
}

// ---------------- pass 2: out = x + A x + b2 -------------------------------------
// grid (NN/128, 2, NB); block 256 (16x16); 128x128 tile, K=256.
__global__ __launch_bounds__(256, 2) void pass2_kernel(const float* __restrict__ x,
                                                       float* __restrict__ out) {
    int b = blockIdx.z;
    int m0 = blockIdx.y * 128;
    int n0 = blockIdx.x * 128;
    __shared__ float As[KT][132];
    __shared__ float Xs[KT][132];
    int tid = threadIdx.x;
    int ty = tid >> 4, tx = tid & 15;
    float acc[8][8] = {};
    const float* xb = x + (size_t)b * C_ * NN;
    const float* Ab = &d_A[b][0][0];

    for (int k0 = 0; k0 < C_; k0 += KT) {
#pragma unroll
        for (int l = 0; l < 4; l++) {
            int lin = tid + l * 256;
            // A tile: [128 rows][8 f4] -> transposed into As[k][m]
            int row = lin >> 3, c4 = lin & 7;
            float4 va = *(const float4*)(Ab + (size_t)(m0 + row) * C_ + (k0 + c4 * 4));
            As[c4 * 4 + 0][row] = va.x; As[c4 * 4 + 1][row] = va.y;
            As[c4 * 4 + 2][row] = va.z; As[c4 * 4 + 3][row] = va.w;
            // X tile: [32 k-rows][32 f4], natural layout Xs[k][n]
            int xrow = lin >> 5, xc4 = lin & 31;
            float4 vx = *(const float4*)(xb + (size_t)(k0 + xrow) * NN + (n0 + xc4 * 4));
            *(float4*)&Xs[xrow][xc4 * 4] = vx;
        }
        __syncthreads();
#pragma unroll
        for (int k = 0; k < KT; k++) {
            float a[8], xv[8];
            *(float4*)(a)      = *(const float4*)&As[k][ty * 8];
            *(float4*)(a + 4)  = *(const float4*)&As[k][ty * 8 + 4];
            *(float4*)(xv)     = *(const float4*)&Xs[k][tx * 8];
            *(float4*)(xv + 4) = *(const float4*)&Xs[k][tx * 8 + 4];
#pragma unroll
            for (int i = 0; i < 8; i++)
#pragma unroll
                for (int j = 0; j < 8; j++) acc[i][j] += a[i] * xv[j];
        }
        __syncthreads();
    }

    // epilogue: out = acc + x + b2  (residual in fp32)
#pragma unroll
    for (int i = 0; i < 8; i++) {
        int c = m0 + ty * 8 + i;
        float bias = d_b2[b][c];
        size_t off = (size_t)(b * C_ + c) * NN + n0 + tx * 8;
        float4 x0 = *(const float4*)(x + off);
        float4 x1 = *(const float4*)(x + off + 4);
        float4 o0, o1;
        o0.x = acc[i][0] + x0.x + bias; o0.y = acc[i][1] + x0.y + bias;
        o0.z = acc[i][2] + x0.z + bias; o0.w = acc[i][3] + x0.w + bias;
        o1.x = acc[i][4] + x1.x + bias; o1.y = acc[i][5] + x1.y + bias;
        o1.z = acc[i][6] + x1.z + bias; o1.w = acc[i][7] + x1.w + bias;
        *(float4*)(out + off)     = o0;
        *(float4*)(out + off + 4) = o1;
    }
}

// ---------------- launch ----------------------------------------------------------
extern "C" void kernel_launch(void* const* d_in, const int* in_sizes, int n_in,
                              void* d_out, int out_size) {
    const float* x       = (const float*)d_in[0];
    const float* g_w     = (const float*)d_in[1];
    const float* g_b     = (const float*)d_in[2];
    const float* theta_w = (const float*)d_in[3];
    const float* theta_b = (const float*)d_in[4];
    const float* phi_w   = (const float*)d_in[5];
    const float* phi_b   = (const float*)d_in[6];
    const float* W_w     = (const float*)d_in[7];
    const float* W_b     = (const float*)d_in[8];
    float* out = (float*)d_out;

    zero_kernel<<<(NB * C_ * C_ + 255) / 256, 256>>>();
    rowsum_kernel<<<dim3(C_, NB), 256>>>(x);
    syrk_kernel<<<dim3(NN / CK, 4, NB), 256>>>(x);
    uv_kernel<<<dim3(1, NB), CI_>>>(phi_w, g_w);
    t1_kernel<<<dim3(CI_, NB), C_>>>(phi_w);
    kv_kernel<<<dim3(CI_, NB), CI_>>>(g_w, g_b, phi_b);
    m_kernel<<<dim3(C_, NB), CI_>>>(W_w);
    a_kernel<<<dim3(C_, NB), C_>>>(theta_w, theta_b, W_b);
    pass2_kernel<<<dim3(NN / 128, 2, NB), 256>>>(x, out);
}

// round 5
// speedup vs baseline: 1.7498x; 1.7498x over previous
#include <cuda_runtime.h>
#include <cuda_bf16.h>
#include <cstdint>
#include <cstddef>

#define NB 2
#define C_ 256
#define CI_ 128
#define NNPOS 65536
#define NCH1 32            // k-chunks per batch, pass1 (256 CTAs)
#define KSPAN1 2048        // NNPOS / NCH1
#define NT2 64             // spatial cols per pass2 tile
#define UNITS 4096         // NB * 2 mhalves * 1024 ntiles
#define TPC 28             // units per CTA pass2 -> 147 CTAs

// ---------------- scratch (static device globals; no allocation) ----------------
__device__ __align__(16) float    d_Sp[(size_t)NB * NCH1 * 4 * 16384]; // partial S, 16MB
__device__ __align__(16) float    d_sps[NB * NCH1 * C_];
__device__ __align__(16) float    d_S[NB * C_ * C_];
__device__ __align__(16) float    d_s[NB * C_];
__device__ __align__(16) float    d_T1[NB * CI_ * C_];
__device__ __align__(16) float    d_u[NB * CI_];
__device__ __align__(16) float    d_v[NB * CI_];
__device__ __align__(16) float    d_kv[NB * CI_ * CI_];
__device__ __align__(16) float    d_M[NB * C_ * CI_];
__device__ __align__(16) float    d_b2[NB * C_];
__device__ __align__(16) uint32_t d_Abh[NB * C_ * CI_];   // A hi bf16x2 [b][m][kpair]
__device__ __align__(16) uint32_t d_Abl[NB * C_ * CI_];   // A lo bf16x2

// ---------------- primitives ----------------
__device__ __forceinline__ uint32_t smem_u32(const void* p) {
    uint32_t a;
    asm("{ .reg .u64 t; cvta.to.shared.u64 t, %1; cvt.u32.u64 %0, t; }" : "=r"(a) : "l"(p));
    return a;
}
__device__ __forceinline__ void mma16816(float* d, const uint32_t* a, const uint32_t* b) {
    asm volatile("mma.sync.aligned.m16n8k16.row.col.f32.bf16.bf16.f32 "
                 "{%0,%1,%2,%3}, {%4,%5,%6,%7}, {%8,%9}, {%0,%1,%2,%3};"
                 : "+f"(d[0]), "+f"(d[1]), "+f"(d[2]), "+f"(d[3])
                 : "r"(a[0]), "r"(a[1]), "r"(a[2]), "r"(a[3]), "r"(b[0]), "r"(b[1]));
}
__device__ __forceinline__ void ldsm4(uint32_t* r, uint32_t addr) {
    asm volatile("ldmatrix.sync.aligned.m8n8.x4.shared.b16 {%0,%1,%2,%3}, [%4];"
                 : "=r"(r[0]), "=r"(r[1]), "=r"(r[2]), "=r"(r[3]) : "r"(addr));
}
__device__ __forceinline__ void ldsm4t(uint32_t* r, uint32_t addr) {
    asm volatile("ldmatrix.sync.aligned.m8n8.x4.trans.shared.b16 {%0,%1,%2,%3}, [%4];"
                 : "=r"(r[0]), "=r"(r[1]), "=r"(r[2]), "=r"(r[3]) : "r"(addr));
}
__device__ __forceinline__ uint32_t sw128(uint32_t byte) { return byte ^ ((byte >> 3) & 0x70u); }
__device__ __forceinline__ uint32_t sw512(uint32_t byte) { return byte ^ ((byte >> 5) & 0x70u); }

// split a float pair into hi/lo bf16x2 packs
__device__ __forceinline__ void split2(float x, float y, uint32_t& h, uint32_t& l) {
    __nv_bfloat162 ph = __floats2bfloat162_rn(x, y);
    __nv_bfloat162 pl = __floats2bfloat162_rn(x - __low2float(ph), y - __high2float(ph));
    h = *(uint32_t*)&ph;
    l = *(uint32_t*)&pl;
}

extern __shared__ uint8_t dsm[];

// ================= pass 1: quadrant syrk (split bf16), partial S + rowsums =======
// grid (4 quads, NCH1, NB), block 256 (8 warps, warp tile 32x64)
__global__ __launch_bounds__(256, 2) void pass1_kernel(const float* __restrict__ x) {
    uint8_t* Ah = dsm;            // 128 x 64 bf16 sw128, 16KB
    uint8_t* Al = dsm + 16384;
    uint8_t* Bh = dsm + 32768;
    uint8_t* Bl = dsm + 49152;

    int quad = blockIdx.x, ch = blockIdx.y, b = blockIdx.z;
    int qm = quad >> 1, qn = quad & 1;
    bool diag = (qm == qn);
    const float* xa = x + ((size_t)(b * C_ + qm * 128)) * NNPOS + (size_t)ch * KSPAN1;
    const float* xb = x + ((size_t)(b * C_ + qn * 128)) * NNPOS + (size_t)ch * KSPAN1;

    int t = threadIdx.x, w = t >> 5, lane = t & 31;
    int lrow = t >> 1, lhalf = t & 1;
    int wm = w >> 1, wn = w & 1;
    int m0 = wm * 32, n0 = wn * 64;

    uint32_t ahb = smem_u32(Ah), alb = smem_u32(Al);
    uint32_t bhb = diag ? ahb : smem_u32(Bh);
    uint32_t blb = diag ? alb : smem_u32(Bl);

    float acc[2][8][4];
#pragma unroll
    for (int i = 0; i < 2; i++)
#pragma unroll
        for (int j = 0; j < 8; j++)
#pragma unroll
            for (int q = 0; q < 4; q++) acc[i][j][q] = 0.f;

    float rs = 0.f;

    for (int kt = 0; kt < KSPAN1 / 64; kt++) {
        // ---- load + split-convert tile(s) ----
        {
            const float* pa = xa + (size_t)lrow * NNPOS + kt * 64 + lhalf * 32;
#pragma unroll
            for (int i = 0; i < 8; i++) {
                float4 v = *(const float4*)(pa + i * 4);
                if (diag) rs += v.x + v.y + v.z + v.w;
                uint32_t h0, l0, h1, l1;
                split2(v.x, v.y, h0, l0);
                split2(v.z, v.w, h1, l1);
                uint32_t byte = (uint32_t)lrow * 128u + (uint32_t)(lhalf * 32 + i * 4) * 2u;
                uint32_t sw = sw128(byte);
                *(uint2*)(Ah + sw) = make_uint2(h0, h1);
                *(uint2*)(Al + sw) = make_uint2(l0, l1);
            }
            if (!diag) {
                const float* pb = xb + (size_t)lrow * NNPOS + kt * 64 + lhalf * 32;
#pragma unroll
                for (int i = 0; i < 8; i++) {
                    float4 v = *(const float4*)(pb + i * 4);
                    uint32_t h0, l0, h1, l1;
                    split2(v.x, v.y, h0, l0);
                    split2(v.z, v.w, h1, l1);
                    uint32_t byte = (uint32_t)lrow * 128u + (uint32_t)(lhalf * 32 + i * 4) * 2u;
                    uint32_t sw = sw128(byte);
                    *(uint2*)(Bh + sw) = make_uint2(h0, h1);
                    *(uint2*)(Bl + sw) = make_uint2(l0, l1);
                }
            }
        }
        __syncthreads();
        // ---- mma: S += Ah Bh^T + Al Bh^T + Ah Bl^T ----
#pragma unroll
        for (int ks = 0; ks < 4; ks++) {
            int k0 = ks * 16;
            uint32_t ah[2][4], al[2][4];
#pragma unroll
            for (int mt = 0; mt < 2; mt++) {
                uint32_t byte = (uint32_t)(m0 + mt * 16 + (lane & 15)) * 128u
                              + (uint32_t)(k0 + (lane >> 4) * 8) * 2u;
                uint32_t sw = sw128(byte);
                ldsm4(ah[mt], ahb + sw);
                ldsm4(al[mt], alb + sw);
            }
            uint32_t bf[8][2];
            int g = lane >> 3, j = lane & 7;
            // B hi
#pragma unroll
            for (int n2 = 0; n2 < 4; n2++) {
                uint32_t row = (uint32_t)(n0 + n2 * 16 + (g >> 1) * 8 + j);
                uint32_t kk  = (uint32_t)(k0 + (g & 1) * 8);
                uint32_t r[4];
                ldsm4(r, bhb + sw128(row * 128u + kk * 2u));
                bf[n2 * 2][0] = r[0]; bf[n2 * 2][1] = r[1];
                bf[n2 * 2 + 1][0] = r[2]; bf[n2 * 2 + 1][1] = r[3];
            }
#pragma unroll
            for (int mt = 0; mt < 2; mt++)
#pragma unroll
                for (int nt = 0; nt < 8; nt++) {
                    mma16816(acc[mt][nt], ah[mt], bf[nt]);
                    mma16816(acc[mt][nt], al[mt], bf[nt]);
                }
            // B lo (overwrite frag regs)
#pragma unroll
            for (int n2 = 0; n2 < 4; n2++) {
                uint32_t row = (uint32_t)(n0 + n2 * 16 + (g >> 1) * 8 + j);
                uint32_t kk  = (uint32_t)(k0 + (g & 1) * 8);
                uint32_t r[4];
                ldsm4(r, blb + sw128(row * 128u + kk * 2u));
                bf[n2 * 2][0] = r[0]; bf[n2 * 2][1] = r[1];
                bf[n2 * 2 + 1][0] = r[2]; bf[n2 * 2 + 1][1] = r[3];
            }
#pragma unroll
            for (int mt = 0; mt < 2; mt++)
#pragma unroll
                for (int nt = 0; nt < 8; nt++)
                    mma16816(acc[mt][nt], ah[mt], bf[nt]);
        }
        __syncthreads();
    }

    // ---- write partial S quadrant ----
    float* Sp = d_Sp + (((size_t)(b * NCH1 + ch) * 4 + quad) << 14);
#pragma unroll
    for (int mt = 0; mt < 2; mt++) {
        int r = m0 + mt * 16 + (lane >> 2);
        int c = n0 + 2 * (lane & 3);
#pragma unroll
        for (int nt = 0; nt < 8; nt++) {
            *(float2*)(Sp + (size_t)r * 128 + c + nt * 8)
                = make_float2(acc[mt][nt][0], acc[mt][nt][1]);
            *(float2*)(Sp + (size_t)(r + 8) * 128 + c + nt * 8)
                = make_float2(acc[mt][nt][2], acc[mt][nt][3]);
        }
    }
    // ---- rowsums (diag quads only) ----
    if (diag) {
        rs += __shfl_xor_sync(0xFFFFFFFFu, rs, 1);
        if (lhalf == 0)
            d_sps[(b * NCH1 + ch) * C_ + qm * 128 + lrow] = rs;
    }
}

// ================= reductions =================
__global__ void reduce_kernel() {
    int e = blockIdx.x * 256 + threadIdx.x;
    int b = e >> 16, r = e & 65535;
    int m = r >> 8, n = r & 255;
    int quad = ((m >> 7) << 1) | (n >> 7);
    size_t off = ((size_t)b * NCH1 * 4 + quad) * 16384 + (size_t)(m & 127) * 128 + (n & 127);
    float acc = 0.f;
#pragma unroll 8
    for (int ch = 0; ch < NCH1; ch++) acc += d_Sp[off + (size_t)ch * 65536];
    d_S[(size_t)b * 65536 + m * 256 + n] = acc;
}
__global__ void rowred_kernel() {
    int b = blockIdx.x, c = threadIdx.x;
    float acc = 0.f;
#pragma unroll 8
    for (int ch = 0; ch < NCH1; ch++) acc += d_sps[(b * NCH1 + ch) * C_ + c];
    d_s[b * C_ + c] = acc;
}

// ================= small chain (fp32) =================
__global__ void stageA_kernel(const float* __restrict__ phi_w, const float* __restrict__ g_w) {
    int b = blockIdx.y;
    __shared__ float srow[C_];
    if (blockIdx.x < CI_) {
        int i = blockIdx.x, j = threadIdx.x;
        srow[j] = phi_w[i * C_ + j];
        __syncthreads();
        const float* Sb = d_S + (size_t)b * 65536;
        float acc = 0.f;
#pragma unroll 8
        for (int c = 0; c < C_; c++) acc += srow[c] * Sb[c * C_ + j];
        d_T1[((size_t)b * CI_ + i) * C_ + j] = acc;
    } else {
        int tt = threadIdx.x;
        srow[tt] = d_s[b * C_ + tt];
        __syncthreads();
        int hf = tt >> 7, i = tt & 127;
        const float* wp = hf ? g_w : phi_w;
        float acc = 0.f;
#pragma unroll 8
        for (int c = 0; c < C_; c++) acc += wp[i * C_ + c] * srow[c];
        if (hf) d_v[b * CI_ + i] = acc; else d_u[b * CI_ + i] = acc;
    }
}
__global__ void stageB_kernel(const float* __restrict__ g_w, const float* __restrict__ g_b,
                              const float* __restrict__ phi_b) {
    int b = blockIdx.y, i = blockIdx.x, j = threadIdx.x;
    __shared__ float st1[C_];
    st1[j]       = d_T1[((size_t)b * CI_ + i) * C_ + j];
    st1[j + 128] = d_T1[((size_t)b * CI_ + i) * C_ + j + 128];
    __syncthreads();
    float acc = 0.f;
#pragma unroll 8
    for (int d = 0; d < C_; d++) acc += st1[d] * g_w[j * C_ + d];
    acc += d_u[b * CI_ + i] * g_b[j] + phi_b[i] * d_v[b * CI_ + j]
         + 65536.0f * phi_b[i] * g_b[j];
    d_kv[((size_t)b * CI_ + i) * CI_ + j] = acc;
}
__global__ void stageC_kernel(const float* __restrict__ W_w) {
    int b = blockIdx.y, mm = blockIdx.x, i = threadIdx.x;
    __shared__ float sw[CI_];
    sw[i] = W_w[mm * CI_ + i];
    __syncthreads();
    const float* kvr = d_kv + ((size_t)b * CI_ + i) * CI_;
    float acc = 0.f;
#pragma unroll 8
    for (int j = 0; j < CI_; j++) acc += sw[j] * kvr[j];
    d_M[((size_t)b * C_ + mm) * CI_ + i] = acc * (1.0f / 65536.0f);
}
__global__ void stageD_kernel(const float* __restrict__ theta_w, const float* __restrict__ theta_b,
                              const float* __restrict__ W_b) {
    int b = blockIdx.y, mm = blockIdx.x, c = threadIdx.x;
    __shared__ float sm[CI_];
    __shared__ float red[CI_];
    sm[c] = d_M[((size_t)b * C_ + mm) * CI_ + c];
    __syncthreads();
    float a0 = 0.f, a1 = 0.f;
#pragma unroll 8
    for (int i = 0; i < CI_; i++) {
        float2 tw = *(const float2*)(theta_w + i * C_ + 2 * c);
        a0 += sm[i] * tw.x;
        a1 += sm[i] * tw.y;
    }
    uint32_t h, l;
    split2(a0, a1, h, l);
    d_Abh[((size_t)b * C_ + mm) * CI_ + c] = h;
    d_Abl[((size_t)b * C_ + mm) * CI_ + c] = l;
    red[c] = sm[c] * theta_b[c];
    __syncthreads();
    for (int s2 = 64; s2 > 0; s2 >>= 1) {
        if (c < s2) red[c] += red[c + s2];
        __syncthreads();
    }
    if (c == 0) d_b2[b * C_ + mm] = red[0] + W_b[mm];
}

// ================= pass 2: out = x + A x + b2 (split bf16, m-half per CTA) =======
// smem: Ah 64KB | Al 64KB | Xh 32KB | Xl 32KB | b2s 512B  (~193KB)
// block 256, 8 warps: 4 m-warps (32 rows each of the 128-row m-half) x 2 n-warps (32 cols)
__global__ __launch_bounds__(256) void pass2_kernel(const float* __restrict__ x,
                                                    float* __restrict__ out) {
    int start = blockIdx.x * TPC;
    int end = start + TPC; if (end > UNITS) end = UNITS;
    if (start >= UNITS) return;

    uint8_t* Ahs = dsm;
    uint8_t* Als = dsm + 65536;
    uint8_t* Xhs = dsm + 131072;
    uint8_t* Xls = dsm + 163840;
    float*   b2s = (float*)(dsm + 196608);
    uint32_t ahb = smem_u32(Ahs), alb = smem_u32(Als);
    uint32_t xhb = smem_u32(Xhs), xlb = smem_u32(Xls);

    int t = threadIdx.x, w = t >> 5, lane = t & 31;
    int m0 = (w >> 1) * 32;          // within m-half
    int n0w = (w & 1) * 32;          // within 64-wide tile
    int prow = t >> 2, pq = t & 3;

    uint32_t Rh[32], Rl[32];
    auto prefetch = [&](int u) {
        int bg = u >> 11, n02 = (u & 1023) * NT2;
#pragma unroll
        for (int p = 0; p < 4; p++) {
            const float* src = x + ((size_t)(bg * C_ + prow + p * 64)) * NNPOS + n02 + pq * 16;
#pragma unroll
            for (int i = 0; i < 4; i++) {
                float4 v = *(const float4*)(src + i * 4);
                split2(v.x, v.y, Rh[p * 8 + i * 2],     Rl[p * 8 + i * 2]);
                split2(v.z, v.w, Rh[p * 8 + i * 2 + 1], Rl[p * 8 + i * 2 + 1]);
            }
        }
    };

    prefetch(start);
    int cur = -1;
    for (int it = 0; it < end - start; it++) {
        int u = start + it;
        int bg = u >> 11, mh = (u >> 10) & 1, n0t = (u & 1023) * NT2;

        __syncthreads();                 // prior mma done; smem reusable
        if ((u >> 10) != cur) {          // load A m-half (hi+lo) + b2
            const uint4* Ah4 = (const uint4*)(d_Abh + ((size_t)(bg * C_ + mh * 128)) * CI_);
            const uint4* Al4 = (const uint4*)(d_Abl + ((size_t)(bg * C_ + mh * 128)) * CI_);
#pragma unroll
            for (int ii = 0; ii < 16; ii++) {
                int idx = ii * 256 + t;          // 4096 uint4: m=idx>>5, chunk=idx&31
                uint32_t byte = (uint32_t)(idx >> 5) * 512u + (uint32_t)(idx & 31) * 16u;
                uint32_t sw = sw512(byte);
                *(uint4*)(Ahs + sw) = Ah4[idx];
                *(uint4*)(Als + sw) = Al4[idx];
            }
            if (t < 128) b2s[t] = d_b2[bg * C_ + mh * 128 + t];
            cur = u >> 10;
        }
        // store prefetched X tile (hi + lo)
#pragma unroll
        for (int p = 0; p < 4; p++) {
            uint32_t rowb = (uint32_t)(prow + p * 64) * 128u;
#pragma unroll
            for (int i = 0; i < 4; i++) {
                uint32_t sw = sw128(rowb + (uint32_t)(pq * 16 + i * 4) * 2u);
                *(uint2*)(Xhs + sw) = make_uint2(Rh[p * 8 + i * 2], Rh[p * 8 + i * 2 + 1]);
                *(uint2*)(Xls + sw) = make_uint2(Rl[p * 8 + i * 2], Rl[p * 8 + i * 2 + 1]);
            }
        }
        __syncthreads();
        if (it + 1 < end - start) prefetch(u + 1);   // overlaps mma

        float acc[2][4][4];
#pragma unroll
        for (int i = 0; i < 2; i++)
#pragma unroll
            for (int j = 0; j < 4; j++)
#pragma unroll
                for (int q = 0; q < 4; q++) acc[i][j][q] = 0.f;

#pragma unroll 4
        for (int ks = 0; ks < 16; ks++) {
            int k0 = ks * 16;
            uint32_t ah[2][4], al[2][4];
#pragma unroll
            for (int mt = 0; mt < 2; mt++) {
                uint32_t byte = (uint32_t)(m0 + mt * 16 + (lane & 15)) * 512u
                              + (uint32_t)(k0 + (lane >> 4) * 8) * 2u;
                uint32_t sw = sw512(byte);
                ldsm4(ah[mt], ahb + sw);
                ldsm4(al[mt], alb + sw);
            }
            uint32_t bf[4][2];
            int g = lane >> 3, j = lane & 7;
            // X hi frags
#pragma unroll
            for (int n2 = 0; n2 < 2; n2++) {
                uint32_t rowk = (uint32_t)(k0 + (g & 1) * 8 + j);
                uint32_t coln = (uint32_t)(n0w + n2 * 16 + (g >> 1) * 8);
                uint32_t r[4];
                ldsm4t(r, xhb + sw128(rowk * 128u + coln * 2u));
                bf[n2 * 2][0] = r[0]; bf[n2 * 2][1] = r[1];
                bf[n2 * 2 + 1][0] = r[2]; bf[n2 * 2 + 1][1] = r[3];
            }
#pragma unroll
            for (int mt = 0; mt < 2; mt++)
#pragma unroll
                for (int nt = 0; nt < 4; nt++) {
                    mma16816(acc[mt][nt], ah[mt], bf[nt]);   // Ah*Xh
                    mma16816(acc[mt][nt], al[mt], bf[nt]);   // Al*Xh
                }
            // X lo frags
#pragma unroll
            for (int n2 = 0; n2 < 2; n2++) {
                uint32_t rowk = (uint32_t)(k0 + (g & 1) * 8 + j);
                uint32_t coln = (uint32_t)(n0w + n2 * 16 + (g >> 1) * 8);
                uint32_t r[4];
                ldsm4t(r, xlb + sw128(rowk * 128u + coln * 2u));
                bf[n2 * 2][0] = r[0]; bf[n2 * 2][1] = r[1];
                bf[n2 * 2 + 1][0] = r[2]; bf[n2 * 2 + 1][1] = r[3];
            }
#pragma unroll
            for (int mt = 0; mt < 2; mt++)
#pragma unroll
                for (int nt = 0; nt < 4; nt++)
                    mma16816(acc[mt][nt], ah[mt], bf[nt]);   // Ah*Xl
        }

        // epilogue: out = acc + x + b2 (fp32 residual; x rows are L2-hot)
#pragma unroll
        for (int mt = 0; mt < 2; mt++) {
            int r = m0 + mt * 16 + (lane >> 2);
            float bv0 = b2s[r], bv1 = b2s[r + 8];
            size_t base0 = ((size_t)(bg * C_ + mh * 128 + r)) * NNPOS + n0t + n0w + 2 * (lane & 3);
            size_t base1 = base0 + (size_t)8 * NNPOS;
#pragma unroll
            for (int nt = 0; nt < 4; nt++) {
                float2 xv = *(const float2*)(x + base0 + nt * 8);
                float2 o;
                o.x = acc[mt][nt][0] + xv.x + bv0;
                o.y = acc[mt][nt][1] + xv.y + bv0;
                *(float2*)(out + base0 + nt * 8) = o;
                xv = *(const float2*)(x + base1 + nt * 8);
                o.x = acc[mt][nt][2] + xv.x + bv1;
                o.y = acc[mt][nt][3] + xv.y + bv1;
                *(float2*)(out + base1 + nt * 8) = o;
            }
        }
    }
}

// ================= launch =================
extern "C" void kernel_launch(void* const* d_in, const int* in_sizes, int n_in,
                              void* d_out, int out_size) {
    const float* x       = (const float*)d_in[0];
    const float* g_w     = (const float*)d_in[1];
    const float* g_b     = (const float*)d_in[2];
    const float* theta_w = (const float*)d_in[3];
    const float* theta_b = (const float*)d_in[4];
    const float* phi_w   = (const float*)d_in[5];
    const float* phi_b   = (const float*)d_in[6];
    const float* W_w     = (const float*)d_in[7];
    const float* W_b     = (const float*)d_in[8];
    float* out = (float*)d_out;

    int smem1 = 65536;                       // 4 x 16KB tiles
    int smem2 = 196608 + 1024;               // Ah+Al+Xh+Xl+b2  (~193KB)
    cudaFuncSetAttribute(pass1_kernel, cudaFuncAttributeMaxDynamicSharedMemorySize, smem1);
    cudaFuncSetAttribute(pass2_kernel, cudaFuncAttributeMaxDynamicSharedMemorySize, smem2);

    pass1_kernel<<<dim3(4, NCH1, NB), 256, smem1>>>(x);
    reduce_kernel<<<512, 256>>>();
    rowred_kernel<<<NB, 256>>>();
    stageA_kernel<<<dim3(CI_ + 1, NB), 256>>>(phi_w, g_w);
    stageB_kernel<<<dim3(CI_, NB), 128>>>(g_w, g_b, phi_b);
    stageC_kernel<<<dim3(C_, NB), 128>>>(W_w);
    stageD_kernel<<<dim3(C_, NB), 128>>>(theta_w, theta_b, W_b);
    pass2_kernel<<<(UNITS + TPC - 1) / TPC, 256, smem2>>>(x, out);
}

// round 7
// speedup vs baseline: 2.3934x; 1.3678x over previous
#include <cuda_runtime.h>
#include <cuda_bf16.h>
#include <cstdint>
#include <cstddef>

#define NB 2
#define C_ 256
#define CI_ 128
#define NNPOS 65536
#define NCH1 49            // uneven k-chunks, pass1: 3 quads x 49 x 2 b = 294 CTAs
#define NT2 64             // spatial cols per pass2 tile
#define UNITS 4096         // NB * 2 mhalves * 1024 ntiles
#define TPC 28             // units per CTA pass2 -> 147 CTAs

// ---------------- scratch (static device globals; no allocation) ----------------
__device__ __align__(16) float    d_Sp[(size_t)NB * NCH1 * 3 * 16384]; // partial S
__device__ __align__(16) float    d_sps[NB * NCH1 * C_];
__device__ __align__(16) float    d_S[NB * C_ * C_];
__device__ __align__(16) float    d_s[NB * C_];
__device__ __align__(16) float    d_gwT[C_ * CI_];        // g_w transposed [d][j]
__device__ __align__(16) float    d_T1[NB * CI_ * C_];
__device__ __align__(16) float    d_u[NB * CI_];
__device__ __align__(16) float    d_v[NB * CI_];
__device__ __align__(16) float    d_kvT[NB * CI_ * CI_];  // kv transposed [b][j][i]
__device__ __align__(16) float    d_M[NB * C_ * CI_];
__device__ __align__(16) float    d_b2[NB * C_];
__device__ __align__(16) uint32_t d_Abh[NB * C_ * CI_];   // A hi bf16x2 [b][m][kpair]
__device__ __align__(16) uint32_t d_Abl[NB * C_ * CI_];   // A lo bf16x2

// ---------------- primitives ----------------
__device__ __forceinline__ uint32_t smem_u32(const void* p) {
    uint32_t a;
    asm("{ .reg .u64 t; cvta.to.shared.u64 t, %1; cvt.u32.u64 %0, t; }" : "=r"(a) : "l"(p));
    return a;
}
__device__ __forceinline__ void mma16816(float* d, const uint32_t* a, const uint32_t* b) {
    asm volatile("mma.sync.aligned.m16n8k16.row.col.f32.bf16.bf16.f32 "
                 "{%0,%1,%2,%3}, {%4,%5,%6,%7}, {%8,%9}, {%0,%1,%2,%3};"
                 : "+f"(d[0]), "+f"(d[1]), "+f"(d[2]), "+f"(d[3])
                 : "r"(a[0]), "r"(a[1]), "r"(a[2]), "r"(a[3]), "r"(b[0]), "r"(b[1]));
}
__device__ __forceinline__ void ldsm4(uint32_t* r, uint32_t addr) {
    asm volatile("ldmatrix.sync.aligned.m8n8.x4.shared.b16 {%0,%1,%2,%3}, [%4];"
                 : "=r"(r[0]), "=r"(r[1]), "=r"(r[2]), "=r"(r[3]) : "r"(addr));
}
__device__ __forceinline__ void ldsm4t(uint32_t* r, uint32_t addr) {
    asm volatile("ldmatrix.sync.aligned.m8n8.x4.trans.shared.b16 {%0,%1,%2,%3}, [%4];"
                 : "=r"(r[0]), "=r"(r[1]), "=r"(r[2]), "=r"(r[3]) : "r"(addr));
}
__device__ __forceinline__ uint32_t sw128(uint32_t byte) { return byte ^ ((byte >> 3) & 0x70u); }
__device__ __forceinline__ uint32_t sw512(uint32_t byte) { return byte ^ ((byte >> 5) & 0x70u); }

__device__ __forceinline__ void split2(float x, float y, uint32_t& h, uint32_t& l) {
    __nv_bfloat162 ph = __floats2bfloat162_rn(x, y);
    __nv_bfloat162 pl = __floats2bfloat162_rn(x - __low2float(ph), y - __high2float(ph));
    h = *(uint32_t*)&ph;
    l = *(uint32_t*)&pl;
}
__device__ __forceinline__ float4 f4fma(float s, float4 q, float4 a) {
    a.x += s * q.x; a.y += s * q.y; a.z += s * q.z; a.w += s * q.w;
    return a;
}

extern __shared__ uint8_t dsm[];

// ================= pass 1: 3-quadrant syrk (split bf16), partial S + rowsums =====
// grid (3, NCH1, NB), block 256 (8 warps, warp tile 32x64)
__global__ __launch_bounds__(256, 2) void pass1_kernel(const float* __restrict__ x) {
    uint8_t* Ah = dsm;            // 128 x 64 bf16 sw128, 16KB each
    uint8_t* Al = dsm + 16384;
    uint8_t* Bh = dsm + 32768;
    uint8_t* Bl = dsm + 49152;

    int qi = blockIdx.x, ch = blockIdx.y, b = blockIdx.z;
    int qm = qi >> 1, qn = (qi + 1) >> 1;   // 0:(0,0) 1:(0,1) 2:(1,1)
    bool diag = (qi != 1);
    int kt0 = (ch * 1024) / NCH1, kt1 = ((ch + 1) * 1024) / NCH1;
    const float* xa = x + ((size_t)(b * C_ + qm * 128)) * NNPOS;
    const float* xb = x + ((size_t)(b * C_ + qn * 128)) * NNPOS;

    int t = threadIdx.x, w = t >> 5, lane = t & 31;
    int lrow = t >> 1, lhalf = t & 1;
    int wm = w >> 1, wn = w & 1;
    int m0 = wm * 32, n0 = wn * 64;

    uint32_t ahb = smem_u32(Ah), alb = smem_u32(Al);
    uint32_t bhb = diag ? ahb : smem_u32(Bh);
    uint32_t blb = diag ? alb : smem_u32(Bl);

    float acc[2][8][4];
#pragma unroll
    for (int i = 0; i < 2; i++)
#pragma unroll
        for (int j = 0; j < 8; j++)
#pragma unroll
            for (int q = 0; q < 4; q++) acc[i][j][q] = 0.f;

    float rs = 0.f;

    for (int kt = kt0; kt < kt1; kt++) {
        // ---- load + split-convert tile(s) ----
        {
            const float* pa = xa + (size_t)lrow * NNPOS + kt * 64 + lhalf * 32;
#pragma unroll
            for (int i = 0; i < 8; i++) {
                float4 v = *(const float4*)(pa + i * 4);
                if (diag) rs += v.x + v.y + v.z + v.w;
                uint32_t h0, l0, h1, l1;
                split2(v.x, v.y, h0, l0);
                split2(v.z, v.w, h1, l1);
                uint32_t byte = (uint32_t)lrow * 128u + (uint32_t)(lhalf * 32 + i * 4) * 2u;
                uint32_t sw = sw128(byte);
                *(uint2*)(Ah + sw) = make_uint2(h0, h1);
                *(uint2*)(Al + sw) = make_uint2(l0, l1);
            }
            if (!diag) {
                const float* pb = xb + (size_t)lrow * NNPOS + kt * 64 + lhalf * 32;
#pragma unroll
                for (int i = 0; i < 8; i++) {
                    float4 v = *(const float4*)(pb + i * 4);
                    uint32_t h0, l0, h1, l1;
                    split2(v.x, v.y, h0, l0);
                    split2(v.z, v.w, h1, l1);
                    uint32_t byte = (uint32_t)lrow * 128u + (uint32_t)(lhalf * 32 + i * 4) * 2u;
                    uint32_t sw = sw128(byte);
                    *(uint2*)(Bh + sw) = make_uint2(h0, h1);
                    *(uint2*)(Bl + sw) = make_uint2(l0, l1);
                }
            }
        }
        __syncthreads();
        // ---- mma: S += Ah Bh^T + Al Bh^T + Ah Bl^T ----
#pragma unroll
        for (int ks = 0; ks < 4; ks++) {
            int k0 = ks * 16;
            uint32_t ah[2][4], al[2][4];
#pragma unroll
            for (int mt = 0; mt < 2; mt++) {
                uint32_t byte = (uint32_t)(m0 + mt * 16 + (lane & 15)) * 128u
                              + (uint32_t)(k0 + (lane >> 4) * 8) * 2u;
                uint32_t sw = sw128(byte);
                ldsm4(ah[mt], ahb + sw);
                ldsm4(al[mt], alb + sw);
            }
            uint32_t bf[8][2];
            int g = lane >> 3, j = lane & 7;
#pragma unroll
            for (int n2 = 0; n2 < 4; n2++) {
                uint32_t row = (uint32_t)(n0 + n2 * 16 + (g >> 1) * 8 + j);
                uint32_t kk  = (uint32_t)(k0 + (g & 1) * 8);
                uint32_t r[4];
                ldsm4(r, bhb + sw128(row * 128u + kk * 2u));
                bf[n2 * 2][0] = r[0]; bf[n2 * 2][1] = r[1];
                bf[n2 * 2 + 1][0] = r[2]; bf[n2 * 2 + 1][1] = r[3];
            }
#pragma unroll
            for (int mt = 0; mt < 2; mt++)
#pragma unroll
                for (int nt = 0; nt < 8; nt++) {
                    mma16816(acc[mt][nt], ah[mt], bf[nt]);
                    mma16816(acc[mt][nt], al[mt], bf[nt]);
                }
#pragma unroll
            for (int n2 = 0; n2 < 4; n2++) {
                uint32_t row = (uint32_t)(n0 + n2 * 16 + (g >> 1) * 8 + j);
                uint32_t kk  = (uint32_t)(k0 + (g & 1) * 8);
                uint32_t r[4];
                ldsm4(r, blb + sw128(row * 128u + kk * 2u));
                bf[n2 * 2][0] = r[0]; bf[n2 * 2][1] = r[1];
                bf[n2 * 2 + 1][0] = r[2]; bf[n2 * 2 + 1][1] = r[3];
            }
#pragma unroll
            for (int mt = 0; mt < 2; mt++)
#pragma unroll
                for (int nt = 0; nt < 8; nt++)
                    mma16816(acc[mt][nt], ah[mt], bf[nt]);
        }
        __syncthreads();
    }

    // ---- write partial S quadrant ----
    float* Sp = d_Sp + (((size_t)(b * NCH1 + ch) * 3 + qi) << 14);
#pragma unroll
    for (int mt = 0; mt < 2; mt++) {
        int r = m0 + mt * 16 + (lane >> 2);
        int c = n0 + 2 * (lane & 3);
#pragma unroll
        for (int nt = 0; nt < 8; nt++) {
            *(float2*)(Sp + (size_t)r * 128 + c + nt * 8)
                = make_float2(acc[mt][nt][0], acc[mt][nt][1]);
            *(float2*)(Sp + (size_t)(r + 8) * 128 + c + nt * 8)
                = make_float2(acc[mt][nt][2], acc[mt][nt][3]);
        }
    }
    if (diag) {
        rs += __shfl_xor_sync(0xFFFFFFFFu, rs, 1);
        if (lhalf == 0)
            d_sps[(b * NCH1 + ch) * C_ + qm * 128 + lrow] = rs;
    }
}

// ================= reduce partial S (quads 0,1,2 -> S blocks) =================
__global__ void reduce_kernel() {
    int id = blockIdx.x * 256 + threadIdx.x;        // 0..24575 float4s
    int b = id / 12288, rest = id % 12288;
    int slot = rest >> 12, idx4 = rest & 4095;
    const float4* p = (const float4*)d_Sp;
    size_t base = ((size_t)b * NCH1 * 3 + slot) * 4096 + idx4;
    float4 a = make_float4(0.f, 0.f, 0.f, 0.f);
#pragma unroll 7
    for (int ch = 0; ch < NCH1; ch++) {
        float4 v = p[base + (size_t)ch * 3 * 4096];
        a.x += v.x; a.y += v.y; a.z += v.z; a.w += v.w;
    }
    int ml = idx4 >> 5, c4 = idx4 & 31;
    int m = (slot == 2) ? 128 + ml : ml;
    int n4 = (slot == 0) ? c4 : 32 + c4;
    ((float4*)d_S)[(size_t)b * 16384 + m * 64 + n4] = a;
}

// ============ fixup: mirror quad(1,0) = quad(0,1)^T ; rowsum reduce ============
__global__ void fixup_kernel() {
    int b = blockIdx.y, t = threadIdx.x;
    if (blockIdx.x < 64) {
        int m = 128 + blockIdx.x * 2 + (t >> 7);
        int j = t & 127;
        d_S[(size_t)b * 65536 + m * 256 + j] = d_S[(size_t)b * 65536 + j * 256 + m];
    } else {
        float acc = 0.f;
#pragma unroll 7
        for (int ch = 0; ch < NCH1; ch++) acc += d_sps[(b * NCH1 + ch) * C_ + t];
        d_s[b * C_ + t] = acc;
    }
}

// ================= one-time transpose of g_w -> d_gwT ==========================
__global__ void gwt_kernel(const float* __restrict__ g_w) {
    __shared__ float tile[32][33];
    int rt = blockIdx.x, ct = blockIdx.y;           // rows/32=4, cols/32=8
    int ty = threadIdx.x >> 5, tx = threadIdx.x & 31;
#pragma unroll
    for (int p = 0; p < 4; p++)
        tile[p * 8 + ty][tx] = g_w[(rt * 32 + p * 8 + ty) * C_ + ct * 32 + tx];
    __syncthreads();
#pragma unroll
    for (int p = 0; p < 4; p++)
        d_gwT[(ct * 32 + p * 8 + ty) * CI_ + rt * 32 + tx] = tile[tx][p * 8 + ty];
}

// ================= chain stages (k-split + float4, all coalesced) ===============
// stageA: T1 = phi_w @ S ; u = phi_w@s, v = g_w@s
__global__ void stageA_kernel(const float* __restrict__ phi_w, const float* __restrict__ g_w) {
    int b = blockIdx.y, t = threadIdx.x;
    if (blockIdx.x < CI_) {
        int i = blockIdx.x;
        __shared__ float ph[C_];
        __shared__ float4 red[4][64];
        ph[t] = phi_w[i * C_ + t];
        __syncthreads();
        int kq = t >> 6, jv = t & 63;
        const float4* S4 = (const float4*)(d_S + (size_t)b * 65536);
        float4 a = make_float4(0.f, 0.f, 0.f, 0.f);
#pragma unroll 8
        for (int c = kq * 64; c < kq * 64 + 64; c++)
            a = f4fma(ph[c], S4[c * 64 + jv], a);
        red[kq][jv] = a;
        __syncthreads();
        if (kq == 0) {
            float4 s0 = red[0][jv], s1 = red[1][jv], s2 = red[2][jv], s3 = red[3][jv];
            float4 o;
            o.x = s0.x + s1.x + s2.x + s3.x; o.y = s0.y + s1.y + s2.y + s3.y;
            o.z = s0.z + s1.z + s2.z + s3.z; o.w = s0.w + s1.w + s2.w + s3.w;
            ((float4*)(d_T1 + ((size_t)b * CI_ + i) * C_))[jv] = o;
        }
    } else {
        __shared__ float ss[C_];
        ss[t] = d_s[b * C_ + t];
        __syncthreads();
        int hf = t >> 7, ii = t & 127;
        const float4* wr = (const float4*)((hf ? g_w : phi_w) + ii * C_);
        const float4* sv = (const float4*)ss;
        float acc = 0.f;
#pragma unroll 8
        for (int q = 0; q < 64; q++) {
            float4 wv = wr[q], s4 = sv[q];
            acc += wv.x * s4.x + wv.y * s4.y + wv.z * s4.z + wv.w * s4.w;
        }
        if (hf) d_v[b * CI_ + ii] = acc; else d_u[b * CI_ + ii] = acc;
    }
}
// stageB: kvT[j][i] = T1[i]·gwT[:,j] + biases
__global__ void stageB_kernel(const float* __restrict__ g_b, const float* __restrict__ phi_b) {
    int b = blockIdx.y, i = blockIdx.x, t = threadIdx.x;
    __shared__ float t1[C_];
    __shared__ float4 red[8][32];
    t1[t] = d_T1[((size_t)b * CI_ + i) * C_ + t];
    __syncthreads();
    int kq = t >> 5, jv = t & 31;
    const float4* Q = (const float4*)d_gwT;           // [256 d][32 f4 j]
    float4 a = make_float4(0.f, 0.f, 0.f, 0.f);
#pragma unroll 8
    for (int d = kq * 32; d < kq * 32 + 32; d++)
        a = f4fma(t1[d], Q[d * 32 + jv], a);
    red[kq][jv] = a;
    __syncthreads();
    if (kq == 0) {
        float4 o = make_float4(0.f, 0.f, 0.f, 0.f);
#pragma unroll
        for (int q = 0; q < 8; q++) {
            float4 v = red[q][jv];
            o.x += v.x; o.y += v.y; o.z += v.z; o.w += v.w;
        }
        float ui = d_u[b * CI_ + i], pb = phi_b[i];
        float4 gb = ((const float4*)g_b)[jv];
        float4 vv = ((const float4*)(d_v + b * CI_))[jv];
        o.x += ui * gb.x + pb * vv.x + 65536.0f * pb * gb.x;
        o.y += ui * gb.y + pb * vv.y + 65536.0f * pb * gb.y;
        o.z += ui * gb.z + pb * vv.z + 65536.0f * pb * gb.z;
        o.w += ui * gb.w + pb * vv.w + 65536.0f * pb * gb.w;
        float* kt = d_kvT + (size_t)b * CI_ * CI_;
        kt[(jv * 4 + 0) * CI_ + i] = o.x;
        kt[(jv * 4 + 1) * CI_ + i] = o.y;
        kt[(jv * 4 + 2) * CI_ + i] = o.z;
        kt[(jv * 4 + 3) * CI_ + i] = o.w;
    }
}
// stageC: M[m][i] = (1/N) W_w[m]·kvT[:,i]
__global__ void stageC_kernel(const float* __restrict__ W_w) {
    int b = blockIdx.y, m = blockIdx.x, t = threadIdx.x;
    __shared__ float ww[CI_];
    __shared__ float4 red[8][32];
    if (t < CI_) ww[t] = W_w[m * CI_ + t];
    __syncthreads();
    int kq = t >> 5, iv = t & 31;
    const float4* Q = (const float4*)(d_kvT + (size_t)b * CI_ * CI_);  // [128 j][32 f4 i]
    float4 a = make_float4(0.f, 0.f, 0.f, 0.f);
#pragma unroll 8
    for (int j = kq * 16; j < kq * 16 + 16; j++)
        a = f4fma(ww[j], Q[j * 32 + iv], a);
    red[kq][iv] = a;
    __syncthreads();
    if (kq == 0) {
        float4 o = make_float4(0.f, 0.f, 0.f, 0.f);
#pragma unroll
        for (int q = 0; q < 8; q++) {
            float4 v = red[q][iv];
            o.x += v.x; o.y += v.y; o.z += v.z; o.w += v.w;
        }
        const float inv = 1.0f / 65536.0f;
        o.x *= inv; o.y *= inv; o.z *= inv; o.w *= inv;
        ((float4*)(d_M + ((size_t)b * C_ + m) * CI_))[iv] = o;
    }
}
// stageD: A[m][:] = M[m]·theta_w (split bf16) ; b2[m] = M[m]·theta_b + W_b[m]
__global__ void stageD_kernel(const float* __restrict__ theta_w, const float* __restrict__ theta_b,
                              const float* __restrict__ W_b) {
    int b = blockIdx.y, m = blockIdx.x, t = threadIdx.x;
    __shared__ float mmv[CI_];
    __shared__ float4 red[4][64];
    __shared__ float bred[CI_];
    if (t < CI_) mmv[t] = d_M[((size_t)b * C_ + m) * CI_ + t];
    __syncthreads();
    int kq = t >> 6, jv = t & 63;
    const float4* Q = (const float4*)theta_w;          // [128 i][64 f4 dd]
    float4 a = make_float4(0.f, 0.f, 0.f, 0.f);
#pragma unroll 8
    for (int i = kq * 32; i < kq * 32 + 32; i++)
        a = f4fma(mmv[i], Q[i * 64 + jv], a);
    red[kq][jv] = a;
    if (t < CI_) bred[t] = mmv[t] * theta_b[t];
    __syncthreads();
    if (kq == 0) {
        float4 s0 = red[0][jv], s1 = red[1][jv], s2 = red[2][jv], s3 = red[3][jv];
        float a0 = s0.x + s1.x + s2.x + s3.x, a1 = s0.y + s1.y + s2.y + s3.y;
        float a2 = s0.z + s1.z + s2.z + s3.z, a3 = s0.w + s1.w + s2.w + s3.w;
        uint32_t h0, l0, h1, l1;
        split2(a0, a1, h0, l0);
        split2(a2, a3, h1, l1);
        size_t base = ((size_t)b * C_ + m) * CI_ + jv * 2;
        d_Abh[base] = h0; d_Abh[base + 1] = h1;
        d_Abl[base] = l0; d_Abl[base + 1] = l1;
    }
    for (int s2v = 64; s2v > 0; s2v >>= 1) {
        if (t < s2v) bred[t] += bred[t + s2v];
        __syncthreads();
    }
    if (t == 0) d_b2[b * C_ + m] = bred[0] + W_b[m];
}

// ================= pass 2: out = x + A x + b2 (split bf16, m-half per CTA) =======
__global__ __launch_bounds__(256) void pass2_kernel(const float* __restrict__ x,
                                                    float* __restrict__ out) {
    int start = blockIdx.x * TPC;
    int end = start + TPC; if (end > UNITS) end = UNITS;
    if (start >= UNITS) return;

    uint8_t* Ahs = dsm;
    uint8_t* Als = dsm + 65536;
    uint8_t* Xhs = dsm + 131072;
    uint8_t* Xls = dsm + 163840;
    float*   b2s = (float*)(dsm + 196608);
    uint32_t ahb = smem_u32(Ahs), alb = smem_u32(Als);
    uint32_t xhb = smem_u32(Xhs), xlb = smem_u32(Xls);

    int t = threadIdx.x, w = t >> 5, lane = t & 31;
    int m0 = (w >> 1) * 32;
    int n0w = (w & 1) * 32;
    int prow = t >> 2, pq = t & 3;

    uint32_t Rh[32], Rl[32];
    auto prefetch = [&](int u) {
        int bg = u >> 11, n02 = (u & 1023) * NT2;
#pragma unroll
        for (int p = 0; p < 4; p++) {
            const float* src = x + ((size_t)(bg * C_ + prow + p * 64)) * NNPOS + n02 + pq * 16;
#pragma unroll
            for (int i = 0; i < 4; i++) {
                float4 v = *(const float4*)(src + i * 4);
                split2(v.x, v.y, Rh[p * 8 + i * 2],     Rl[p * 8 + i * 2]);
                split2(v.z, v.w, Rh[p * 8 + i * 2 + 1], Rl[p * 8 + i * 2 + 1]);
            }
        }
    };

    prefetch(start);
    int cur = -1;
    for (int it = 0; it < end - start; it++) {
        int u = start + it;
        int bg = u >> 11, mh = (u >> 10) & 1, n0t = (u & 1023) * NT2;

        __syncthreads();
        if ((u >> 10) != cur) {
            const uint4* Ah4 = (const uint4*)(d_Abh + ((size_t)(bg * C_ + mh * 128)) * CI_);
            const uint4* Al4 = (const uint4*)(d_Abl + ((size_t)(bg * C_ + mh * 128)) * CI_);
#pragma unroll
            for (int ii = 0; ii < 16; ii++) {
                int idx = ii * 256 + t;
                uint32_t byte = (uint32_t)(idx >> 5) * 512u + (uint32_t)(idx & 31) * 16u;
                uint32_t sw = sw512(byte);
                *(uint4*)(Ahs + sw) = Ah4[idx];
                *(uint4*)(Als + sw) = Al4[idx];
            }
            if (t < 128) b2s[t] = d_b2[bg * C_ + mh * 128 + t];
            cur = u >> 10;
        }
#pragma unroll
        for (int p = 0; p < 4; p++) {
            uint32_t rowb = (uint32_t)(prow + p * 64) * 128u;
#pragma unroll
            for (int i = 0; i < 4; i++) {
                uint32_t sw = sw128(rowb + (uint32_t)(pq * 16 + i * 4) * 2u);
                *(uint2*)(Xhs + sw) = make_uint2(Rh[p * 8 + i * 2], Rh[p * 8 + i * 2 + 1]);
                *(uint2*)(Xls + sw) = make_uint2(Rl[p * 8 + i * 2], Rl[p * 8 + i * 2 + 1]);
            }
        }
        __syncthreads();
        if (it + 1 < end - start) prefetch(u + 1);

        float acc[2][4][4];
#pragma unroll
        for (int i = 0; i < 2; i++)
#pragma unroll
            for (int j = 0; j < 4; j++)
#pragma unroll
                for (int q = 0; q < 4; q++) acc[i][j][q] = 0.f;

#pragma unroll 4
        for (int ks = 0; ks < 16; ks++) {
            int k0 = ks * 16;
            uint32_t ah[2][4], al[2][4];
#pragma unroll
            for (int mt = 0; mt < 2; mt++) {
                uint32_t byte = (uint32_t)(m0 + mt * 16 + (lane & 15)) * 512u
                              + (uint32_t)(k0 + (lane >> 4) * 8) * 2u;
                uint32_t sw = sw512(byte);
                ldsm4(ah[mt], ahb + sw);
                ldsm4(al[mt], alb + sw);
            }
            uint32_t bf[4][2];
            int g = lane >> 3, j = lane & 7;
#pragma unroll
            for (int n2 = 0; n2 < 2; n2++) {
                uint32_t rowk = (uint32_t)(k0 + (g & 1) * 8 + j);
                uint32_t coln = (uint32_t)(n0w + n2 * 16 + (g >> 1) * 8);
                uint32_t r[4];
                ldsm4t(r, xhb + sw128(rowk * 128u + coln * 2u));
                bf[n2 * 2][0] = r[0]; bf[n2 * 2][1] = r[1];
                bf[n2 * 2 + 1][0] = r[2]; bf[n2 * 2 + 1][1] = r[3];
            }
#pragma unroll
            for (int mt = 0; mt < 2; mt++)
#pragma unroll
                for (int nt = 0; nt < 4; nt++) {
                    mma16816(acc[mt][nt], ah[mt], bf[nt]);
                    mma16816(acc[mt][nt], al[mt], bf[nt]);
                }
#pragma unroll
            for (int n2 = 0; n2 < 2; n2++) {
                uint32_t rowk = (uint32_t)(k0 + (g & 1) * 8 + j);
                uint32_t coln = (uint32_t)(n0w + n2 * 16 + (g >> 1) * 8);
                uint32_t r[4];
                ldsm4t(r, xlb + sw128(rowk * 128u + coln * 2u));
                bf[n2 * 2][0] = r[0]; bf[n2 * 2][1] = r[1];
                bf[n2 * 2 + 1][0] = r[2]; bf[n2 * 2 + 1][1] = r[3];
            }
#pragma unroll
            for (int mt = 0; mt < 2; mt++)
#pragma unroll
                for (int nt = 0; nt < 4; nt++)
                    mma16816(acc[mt][nt], ah[mt], bf[nt]);
        }

#pragma unroll
        for (int mt = 0; mt < 2; mt++) {
            int r = m0 + mt * 16 + (lane >> 2);
            float bv0 = b2s[r], bv1 = b2s[r + 8];
            size_t base0 = ((size_t)(bg * C_ + mh * 128 + r)) * NNPOS + n0t + n0w + 2 * (lane & 3);
            size_t base1 = base0 + (size_t)8 * NNPOS;
#pragma unroll
            for (int nt = 0; nt < 4; nt++) {
                float2 xv = *(const float2*)(x + base0 + nt * 8);
                float2 o;
                o.x = acc[mt][nt][0] + xv.x + bv0;
                o.y = acc[mt][nt][1] + xv.y + bv0;
                *(float2*)(out + base0 + nt * 8) = o;
                xv = *(const float2*)(x + base1 + nt * 8);
                o.x = acc[mt][nt][2] + xv.x + bv1;
                o.y = acc[mt][nt][3] + xv.y + bv1;
                *(float2*)(out + base1 + nt * 8) = o;
            }
        }
    }
}

// ================= launch =================
extern "C" void kernel_launch(void* const* d_in, const int* in_sizes, int n_in,
                              void* d_out, int out_size) {
    const float* x       = (const float*)d_in[0];
    const float* g_w     = (const float*)d_in[1];
    const float* g_b     = (const float*)d_in[2];
    const float* theta_w = (const float*)d_in[3];
    const float* theta_b = (const float*)d_in[4];
    const float* phi_w   = (const float*)d_in[5];
    const float* phi_b   = (const float*)d_in[6];
    const float* W_w     = (const float*)d_in[7];
    const float* W_b     = (const float*)d_in[8];
    float* out = (float*)d_out;

    int smem1 = 65536;
    int smem2 = 196608 + 1024;
    cudaFuncSetAttribute(pass1_kernel, cudaFuncAttributeMaxDynamicSharedMemorySize, smem1);
    cudaFuncSetAttribute(pass2_kernel, cudaFuncAttributeMaxDynamicSharedMemorySize, smem2);

    gwt_kernel<<<dim3(4, 8), 256>>>(g_w);
    pass1_kernel<<<dim3(3, NCH1, NB), 256, smem1>>>(x);
    reduce_kernel<<<96, 256>>>();
    fixup_kernel<<<dim3(65, NB), 256>>>();
    stageA_kernel<<<dim3(CI_ + 1, NB), 256>>>(phi_w, g_w);
    stageB_kernel<<<dim3(CI_, NB), 256>>>(g_b, phi_b);
    stageC_kernel<<<dim3(C_, NB), 256>>>(W_w);
    stageD_kernel<<<dim3(C_, NB), 256>>>(theta_w, theta_b, W_b);
    pass2_kernel<<<(UNITS + TPC - 1) / TPC, 256, smem2>>>(x, out);
}

// round 9
// speedup vs baseline: 3.3893x; 1.4161x over previous
#include <cuda_runtime.h>
#include <cuda_bf16.h>
#include <cuda_fp16.h>
#include <cstdint>
#include <cstddef>

#define NB 2
#define C_ 256
#define CI_ 128
#define NNPOS 65536
#define NCH1 49            // uneven k-chunks, pass1: 3 quads x 49 x 2 b = 294 CTAs
#define NT2 64             // spatial cols per pass2 tile
#define UNITS 4096         // NB * 2 mhalves * 1024 ntiles
#define TPC 14             // units per CTA pass2 -> 293 CTAs (occ 2)

// ---------------- scratch (static device globals; no allocation) ----------------
__device__ __align__(16) float    d_Sp[(size_t)NB * NCH1 * 3 * 16384]; // partial S
__device__ __align__(16) float    d_sps[NB * NCH1 * C_];
__device__ __align__(16) float    d_S[NB * C_ * C_];
__device__ __align__(16) float    d_s[NB * C_];
__device__ __align__(16) float    d_gwT[C_ * CI_];        // g_w transposed [d][j]
__device__ __align__(16) float    d_T1[NB * CI_ * C_];
__device__ __align__(16) float    d_u[NB * CI_];
__device__ __align__(16) float    d_v[NB * CI_];
__device__ __align__(16) float    d_kvT[NB * CI_ * CI_];  // kv transposed [b][j][i]
__device__ __align__(16) float    d_M[NB * C_ * CI_];
__device__ __align__(16) float    d_b2[NB * C_];
__device__ __align__(16) uint32_t d_Ah16[NB * C_ * CI_];  // A fp16x2 [b][m][kpair]

// ---------------- primitives ----------------
__device__ __forceinline__ uint32_t smem_u32(const void* p) {
    uint32_t a;
    asm("{ .reg .u64 t; cvta.to.shared.u64 t, %1; cvt.u32.u64 %0, t; }" : "=r"(a) : "l"(p));
    return a;
}
__device__ __forceinline__ void mma16816h(float* d, const uint32_t* a, const uint32_t* b) {
    asm volatile("mma.sync.aligned.m16n8k16.row.col.f32.f16.f16.f32 "
                 "{%0,%1,%2,%3}, {%4,%5,%6,%7}, {%8,%9}, {%0,%1,%2,%3};"
                 : "+f"(d[0]), "+f"(d[1]), "+f"(d[2]), "+f"(d[3])
                 : "r"(a[0]), "r"(a[1]), "r"(a[2]), "r"(a[3]), "r"(b[0]), "r"(b[1]));
}
__device__ __forceinline__ void ldsm4(uint32_t* r, uint32_t addr) {
    asm volatile("ldmatrix.sync.aligned.m8n8.x4.shared.b16 {%0,%1,%2,%3}, [%4];"
                 : "=r"(r[0]), "=r"(r[1]), "=r"(r[2]), "=r"(r[3]) : "r"(addr));
}
__device__ __forceinline__ void ldsm4t(uint32_t* r, uint32_t addr) {
    asm volatile("ldmatrix.sync.aligned.m8n8.x4.trans.shared.b16 {%0,%1,%2,%3}, [%4];"
                 : "=r"(r[0]), "=r"(r[1]), "=r"(r[2]), "=r"(r[3]) : "r"(addr));
}
__device__ __forceinline__ uint32_t sw128(uint32_t byte) { return byte ^ ((byte >> 3) & 0x70u); }
__device__ __forceinline__ uint32_t sw512(uint32_t byte) { return byte ^ ((byte >> 5) & 0x70u); }

__device__ __forceinline__ uint32_t packh(float x, float y) {
    __half2 h = __floats2half2_rn(x, y);
    return *(uint32_t*)&h;
}
__device__ __forceinline__ float4 f4fma(float s, float4 q, float4 a) {
    a.x += s * q.x; a.y += s * q.y; a.z += s * q.z; a.w += s * q.w;
    return a;
}

extern __shared__ uint8_t dsm[];

// ================= pass 1: 3-quadrant syrk (fp16), partial S + rowsums ==========
// grid (3, NCH1, NB), block 256 (8 warps, warp tile 32x64)
__global__ __launch_bounds__(256, 2) void pass1_kernel(const float* __restrict__ x) {
    uint8_t* Ah = dsm;            // 128 x 64 fp16 sw128, 16KB each
    uint8_t* Bh = dsm + 16384;

    int qi = blockIdx.x, ch = blockIdx.y, b = blockIdx.z;
    int qm = qi >> 1, qn = (qi + 1) >> 1;   // 0:(0,0) 1:(0,1) 2:(1,1)
    bool diag = (qi != 1);
    int kt0 = (ch * 1024) / NCH1, kt1 = ((ch + 1) * 1024) / NCH1;
    const float* xa = x + ((size_t)(b * C_ + qm * 128)) * NNPOS;
    const float* xb = x + ((size_t)(b * C_ + qn * 128)) * NNPOS;

    int t = threadIdx.x, w = t >> 5, lane = t & 31;
    int lrow = t >> 1, lhalf = t & 1;
    int wm = w >> 1, wn = w & 1;
    int m0 = wm * 32, n0 = wn * 64;

    uint32_t ahb = smem_u32(Ah);
    uint32_t bhb = diag ? ahb : smem_u32(Bh);

    float acc[2][8][4];
#pragma unroll
    for (int i = 0; i < 2; i++)
#pragma unroll
        for (int j = 0; j < 8; j++)
#pragma unroll
            for (int q = 0; q < 4; q++) acc[i][j][q] = 0.f;

    float rs = 0.f;

    for (int kt = kt0; kt < kt1; kt++) {
        // ---- load + convert tile(s) ----
        {
            const float* pa = xa + (size_t)lrow * NNPOS + kt * 64 + lhalf * 32;
#pragma unroll
            for (int i = 0; i < 8; i++) {
                float4 v = *(const float4*)(pa + i * 4);
                if (diag) rs += v.x + v.y + v.z + v.w;
                uint32_t byte = (uint32_t)lrow * 128u + (uint32_t)(lhalf * 32 + i * 4) * 2u;
                *(uint2*)(Ah + sw128(byte)) = make_uint2(packh(v.x, v.y), packh(v.z, v.w));
            }
            if (!diag) {
                const float* pb = xb + (size_t)lrow * NNPOS + kt * 64 + lhalf * 32;
#pragma unroll
                for (int i = 0; i < 8; i++) {
                    float4 v = *(const float4*)(pb + i * 4);
                    uint32_t byte = (uint32_t)lrow * 128u + (uint32_t)(lhalf * 32 + i * 4) * 2u;
                    *(uint2*)(Bh + sw128(byte)) = make_uint2(packh(v.x, v.y), packh(v.z, v.w));
                }
            }
        }
        __syncthreads();
        // ---- mma (single fp16 pass) ----
#pragma unroll
        for (int ks = 0; ks < 4; ks++) {
            int k0 = ks * 16;
            uint32_t ah[2][4];
#pragma unroll
            for (int mt = 0; mt < 2; mt++) {
                uint32_t byte = (uint32_t)(m0 + mt * 16 + (lane & 15)) * 128u
                              + (uint32_t)(k0 + (lane >> 4) * 8) * 2u;
                ldsm4(ah[mt], ahb + sw128(byte));
            }
            uint32_t bf[8][2];
            int g = lane >> 3, j = lane & 7;
#pragma unroll
            for (int n2 = 0; n2 < 4; n2++) {
                uint32_t row = (uint32_t)(n0 + n2 * 16 + (g >> 1) * 8 + j);
                uint32_t kk  = (uint32_t)(k0 + (g & 1) * 8);
                uint32_t r[4];
                ldsm4(r, bhb + sw128(row * 128u + kk * 2u));
                bf[n2 * 2][0] = r[0]; bf[n2 * 2][1] = r[1];
                bf[n2 * 2 + 1][0] = r[2]; bf[n2 * 2 + 1][1] = r[3];
            }
#pragma unroll
            for (int mt = 0; mt < 2; mt++)
#pragma unroll
                for (int nt = 0; nt < 8; nt++)
                    mma16816h(acc[mt][nt], ah[mt], bf[nt]);
        }
        __syncthreads();
    }

    // ---- write partial S quadrant ----
    float* Sp = d_Sp + (((size_t)(b * NCH1 + ch) * 3 + qi) << 14);
#pragma unroll
    for (int mt = 0; mt < 2; mt++) {
        int r = m0 + mt * 16 + (lane >> 2);
        int c = n0 + 2 * (lane & 3);
#pragma unroll
        for (int nt = 0; nt < 8; nt++) {
            *(float2*)(Sp + (size_t)r * 128 + c + nt * 8)
                = make_float2(acc[mt][nt][0], acc[mt][nt][1]);
            *(float2*)(Sp + (size_t)(r + 8) * 128 + c + nt * 8)
                = make_float2(acc[mt][nt][2], acc[mt][nt][3]);
        }
    }
    if (diag) {
        rs += __shfl_xor_sync(0xFFFFFFFFu, rs, 1);
        if (lhalf == 0)
            d_sps[(b * NCH1 + ch) * C_ + qm * 128 + lrow] = rs;
    }
}

// ================= reduce partial S (quads 0,1,2 -> S blocks) =================
__global__ void reduce_kernel() {
    int id = blockIdx.x * 256 + threadIdx.x;        // 0..24575 float4s
    int b = id / 12288, rest = id % 12288;
    int slot = rest >> 12, idx4 = rest & 4095;
    const float4* p = (const float4*)d_Sp;
    size_t base = ((size_t)b * NCH1 * 3 + slot) * 4096 + idx4;
    float4 a = make_float4(0.f, 0.f, 0.f, 0.f);
#pragma unroll 7
    for (int ch = 0; ch < NCH1; ch++) {
        float4 v = p[base + (size_t)ch * 3 * 4096];
        a.x += v.x; a.y += v.y; a.z += v.z; a.w += v.w;
    }
    int ml = idx4 >> 5, c4 = idx4 & 31;
    int m = (slot == 2) ? 128 + ml : ml;
    int n4 = (slot == 0) ? c4 : 32 + c4;
    ((float4*)d_S)[(size_t)b * 16384 + m * 64 + n4] = a;
}

// ============ fixup: mirror quad(1,0) = quad(0,1)^T ; rowsum reduce ============
__global__ void fixup_kernel() {
    int b = blockIdx.y, t = threadIdx.x;
    if (blockIdx.x < 64) {
        int m = 128 + blockIdx.x * 2 + (t >> 7);
        int j = t & 127;
        d_S[(size_t)b * 65536 + m * 256 + j] = d_S[(size_t)b * 65536 + j * 256 + m];
    } else {
        float acc = 0.f;
#pragma unroll 7
        for (int ch = 0; ch < NCH1; ch++) acc += d_sps[(b * NCH1 + ch) * C_ + t];
        d_s[b * C_ + t] = acc;
    }
}

// ================= one-time transpose of g_w -> d_gwT ==========================
__global__ void gwt_kernel(const float* __restrict__ g_w) {
    __shared__ float tile[32][33];
    int rt = blockIdx.x, ct = blockIdx.y;
    int ty = threadIdx.x >> 5, tx = threadIdx.x & 31;
#pragma unroll
    for (int p = 0; p < 4; p++)
        tile[p * 8 + ty][tx] = g_w[(rt * 32 + p * 8 + ty) * C_ + ct * 32 + tx];
    __syncthreads();
#pragma unroll
    for (int p = 0; p < 4; p++)
        d_gwT[(ct * 32 + p * 8 + ty) * CI_ + rt * 32 + tx] = tile[tx][p * 8 + ty];
}

// ================= chain stages =================
__global__ void stageA_kernel(const float* __restrict__ phi_w, const float* __restrict__ g_w) {
    int b = blockIdx.y, t = threadIdx.x;
    if (blockIdx.x < CI_) {
        int i = blockIdx.x;
        __shared__ float ph[C_];
        __shared__ float4 red[4][64];
        ph[t] = phi_w[i * C_ + t];
        __syncthreads();
        int kq = t >> 6, jv = t & 63;
        const float4* S4 = (const float4*)(d_S + (size_t)b * 65536);
        float4 a = make_float4(0.f, 0.f, 0.f, 0.f);
#pragma unroll 8
        for (int c = kq * 64; c < kq * 64 + 64; c++)
            a = f4fma(ph[c], S4[c * 64 + jv], a);
        red[kq][jv] = a;
        __syncthreads();
        if (kq == 0) {
            float4 s0 = red[0][jv], s1 = red[1][jv], s2 = red[2][jv], s3 = red[3][jv];
            float4 o;
            o.x = s0.x + s1.x + s2.x + s3.x; o.y = s0.y + s1.y + s2.y + s3.y;
            o.z = s0.z + s1.z + s2.z + s3.z; o.w = s0.w + s1.w + s2.w + s3.w;
            ((float4*)(d_T1 + ((size_t)b * CI_ + i) * C_))[jv] = o;
        }
    } else {
        __shared__ float ss[C_];
        ss[t] = d_s[b * C_ + t];
        __syncthreads();
        int hf = t >> 7, ii = t & 127;
        const float4* wr = (const float4*)((hf ? g_w : phi_w) + ii * C_);
        const float4* sv = (const float4*)ss;
        float acc = 0.f;
#pragma unroll 8
        for (int q = 0; q < 64; q++) {
            float4 wv = wr[q], s4 = sv[q];
            acc += wv.x * s4.x + wv.y * s4.y + wv.z * s4.z + wv.w * s4.w;
        }
        if (hf) d_v[b * CI_ + ii] = acc; else d_u[b * CI_ + ii] = acc;
    }
}
__global__ void stageB_kernel(const float* __restrict__ g_b, const float* __restrict__ phi_b) {
    int b = blockIdx.y, i = blockIdx.x, t = threadIdx.x;
    __shared__ float t1[C_];
    __shared__ float4 red[8][32];
    t1[t] = d_T1[((size_t)b * CI_ + i) * C_ + t];
    __syncthreads();
    int kq = t >> 5, jv = t & 31;
    const float4* Q = (const float4*)d_gwT;
    float4 a = make_float4(0.f, 0.f, 0.f, 0.f);
#pragma unroll 8
    for (int d = kq * 32; d < kq * 32 + 32; d++)
        a = f4fma(t1[d], Q[d * 32 + jv], a);
    red[kq][jv] = a;
    __syncthreads();
    if (kq == 0) {
        float4 o = make_float4(0.f, 0.f, 0.f, 0.f);
#pragma unroll
        for (int q = 0; q < 8; q++) {
            float4 v = red[q][jv];
            o.x += v.x; o.y += v.y; o.z += v.z; o.w += v.w;
        }
        float ui = d_u[b * CI_ + i], pb = phi_b[i];
        float4 gb = ((const float4*)g_b)[jv];
        float4 vv = ((const float4*)(d_v + b * CI_))[jv];
        o.x += ui * gb.x + pb * vv.x + 65536.0f * pb * gb.x;
        o.y += ui * gb.y + pb * vv.y + 65536.0f * pb * gb.y;
        o.z += ui * gb.z + pb * vv.z + 65536.0f * pb * gb.z;
        o.w += ui * gb.w + pb * vv.w + 65536.0f * pb * gb.w;
        float* kt = d_kvT + (size_t)b * CI_ * CI_;
        kt[(jv * 4 + 0) * CI_ + i] = o.x;
        kt[(jv * 4 + 1) * CI_ + i] = o.y;
        kt[(jv * 4 + 2) * CI_ + i] = o.z;
        kt[(jv * 4 + 3) * CI_ + i] = o.w;
    }
}
__global__ void stageC_kernel(const float* __restrict__ W_w) {
    int b = blockIdx.y, m = blockIdx.x, t = threadIdx.x;
    __shared__ float ww[CI_];
    __shared__ float4 red[8][32];
    if (t < CI_) ww[t] = W_w[m * CI_ + t];
    __syncthreads();
    int kq = t >> 5, iv = t & 31;
    const float4* Q = (const float4*)(d_kvT + (size_t)b * CI_ * CI_);
    float4 a = make_float4(0.f, 0.f, 0.f, 0.f);
#pragma unroll 8
    for (int j = kq * 16; j < kq * 16 + 16; j++)
        a = f4fma(ww[j], Q[j * 32 + iv], a);
    red[kq][iv] = a;
    __syncthreads();
    if (kq == 0) {
        float4 o = make_float4(0.f, 0.f, 0.f, 0.f);
#pragma unroll
        for (int q = 0; q < 8; q++) {
            float4 v = red[q][iv];
            o.x += v.x; o.y += v.y; o.z += v.z; o.w += v.w;
        }
        const float inv = 1.0f / 65536.0f;
        o.x *= inv; o.y *= inv; o.z *= inv; o.w *= inv;
        ((float4*)(d_M + ((size_t)b * C_ + m) * CI_))[iv] = o;
    }
}
__global__ void stageD_kernel(const float* __restrict__ theta_w, const float* __restrict__ theta_b,
                              const float* __restrict__ W_b) {
    int b = blockIdx.y, m = blockIdx.x, t = threadIdx.x;
    __shared__ float mmv[CI_];
    __shared__ float4 red[4][64];
    __shared__ float bred[CI_];
    if (t < CI_) mmv[t] = d_M[((size_t)b * C_ + m) * CI_ + t];
    __syncthreads();
    int kq = t >> 6, jv = t & 63;
    const float4* Q = (const float4*)theta_w;
    float4 a = make_float4(0.f, 0.f, 0.f, 0.f);
#pragma unroll 8
    for (int i = kq * 32; i < kq * 32 + 32; i++)
        a = f4fma(mmv[i], Q[i * 64 + jv], a);
    red[kq][jv] = a;
    if (t < CI_) bred[t] = mmv[t] * theta_b[t];
    __syncthreads();
    if (kq == 0) {
        float4 s0 = red[0][jv], s1 = red[1][jv], s2 = red[2][jv], s3 = red[3][jv];
        float a0 = s0.x + s1.x + s2.x + s3.x, a1 = s0.y + s1.y + s2.y + s3.y;
        float a2 = s0.z + s1.z + s2.z + s3.z, a3 = s0.w + s1.w + s2.w + s3.w;
        size_t base = ((size_t)b * C_ + m) * CI_ + jv * 2;
        d_Ah16[base]     = packh(a0, a1);
        d_Ah16[base + 1] = packh(a2, a3);
    }
    for (int s2v = 64; s2v > 0; s2v >>= 1) {
        if (t < s2v) bred[t] += bred[t + s2v];
        __syncthreads();
    }
    if (t == 0) d_b2[b * C_ + m] = bred[0] + W_b[m];
}

// ================= pass 2: out = x + A x + b2 (fp16, m-half per CTA, occ 2) ======
// smem: A 64KB | X 32KB | b2 512B (~97KB)
__global__ __launch_bounds__(256, 2) void pass2_kernel(const float* __restrict__ x,
                                                       float* __restrict__ out) {
    int start = blockIdx.x * TPC;
    int end = start + TPC; if (end > UNITS) end = UNITS;
    if (start >= UNITS) return;

    uint8_t* Ahs = dsm;
    uint8_t* Xhs = dsm + 65536;
    float*   b2s = (float*)(dsm + 98304);
    uint32_t ahb = smem_u32(Ahs), xhb = smem_u32(Xhs);

    int t = threadIdx.x, w = t >> 5, lane = t & 31;
    int m0 = (w >> 1) * 32;
    int n0w = (w & 1) * 32;
    int prow = t >> 2, pq = t & 3;

    uint32_t Rh[32];
    auto prefetch = [&](int u) {
        int bg = u >> 11, n02 = (u & 1023) * NT2;
#pragma unroll
        for (int p = 0; p < 4; p++) {
            const float* src = x + ((size_t)(bg * C_ + prow + p * 64)) * NNPOS + n02 + pq * 16;
#pragma unroll
            for (int i = 0; i < 4; i++) {
                float4 v = *(const float4*)(src + i * 4);
                Rh[p * 8 + i * 2]     = packh(v.x, v.y);
                Rh[p * 8 + i * 2 + 1] = packh(v.z, v.w);
            }
        }
    };

    prefetch(start);
    int cur = -1;
    for (int it = 0; it < end - start; it++) {
        int u = start + it;
        int bg = u >> 11, mh = (u >> 10) & 1, n0t = (u & 1023) * NT2;

        __syncthreads();
        if ((u >> 10) != cur) {
            const uint4* Ah4 = (const uint4*)(d_Ah16 + ((size_t)(bg * C_ + mh * 128)) * CI_);
#pragma unroll
            for (int ii = 0; ii < 16; ii++) {
                int idx = ii * 256 + t;
                uint32_t byte = (uint32_t)(idx >> 5) * 512u + (uint32_t)(idx & 31) * 16u;
                *(uint4*)(Ahs + sw512(byte)) = Ah4[idx];
            }
            if (t < 128) b2s[t] = d_b2[bg * C_ + mh * 128 + t];
            cur = u >> 10;
        }
#pragma unroll
        for (int p = 0; p < 4; p++) {
            uint32_t rowb = (uint32_t)(prow + p * 64) * 128u;
#pragma unroll
            for (int i = 0; i < 4; i++) {
                uint32_t sw = sw128(rowb + (uint32_t)(pq * 16 + i * 4) * 2u);
                *(uint2*)(Xhs + sw) = make_uint2(Rh[p * 8 + i * 2], Rh[p * 8 + i * 2 + 1]);
            }
        }
        __syncthreads();
        if (it + 1 < end - start) prefetch(u + 1);    // overlaps mma below

        float acc[2][4][4];
#pragma unroll
        for (int i = 0; i < 2; i++)
#pragma unroll
            for (int j = 0; j < 4; j++)
#pragma unroll
                for (int q = 0; q < 4; q++) acc[i][j][q] = 0.f;

#pragma unroll 4
        for (int ks = 0; ks < 16; ks++) {
            int k0 = ks * 16;
            uint32_t ah[2][4];
#pragma unroll
            for (int mt = 0; mt < 2; mt++) {
                uint32_t byte = (uint32_t)(m0 + mt * 16 + (lane & 15)) * 512u
                              + (uint32_t)(k0 + (lane >> 4) * 8) * 2u;
                ldsm4(ah[mt], ahb + sw512(byte));
            }
            uint32_t bf[4][2];
            int g = lane >> 3, j = lane & 7;
#pragma unroll
            for (int n2 = 0; n2 < 2; n2++) {
                uint32_t rowk = (uint32_t)(k0 + (g & 1) * 8 + j);
                uint32_t coln = (uint32_t)(n0w + n2 * 16 + (g >> 1) * 8);
                uint32_t r[4];
                ldsm4t(r, xhb + sw128(rowk * 128u + coln * 2u));
                bf[n2 * 2][0] = r[0]; bf[n2 * 2][1] = r[1];
                bf[n2 * 2 + 1][0] = r[2]; bf[n2 * 2 + 1][1] = r[3];
            }
#pragma unroll
            for (int mt = 0; mt < 2; mt++)
#pragma unroll
                for (int nt = 0; nt < 4; nt++)
                    mma16816h(acc[mt][nt], ah[mt], bf[nt]);
        }

        // epilogue: out = acc + x + b2 (fp32 residual; x rows L2-hot)
#pragma unroll
        for (int mt = 0; mt < 2; mt++) {
            int r = m0 + mt * 16 + (lane >> 2);
            float bv0 = b2s[r], bv1 = b2s[r + 8];
            size_t base0 = ((size_t)(bg * C_ + mh * 128 + r)) * NNPOS + n0t + n0w + 2 * (lane & 3);
            size_t base1 = base0 + (size_t)8 * NNPOS;
#pragma unroll
            for (int nt = 0; nt < 4; nt++) {
                float2 xv = *(const float2*)(x + base0 + nt * 8);
                float2 o;
                o.x = acc[mt][nt][0] + xv.x + bv0;
                o.y = acc[mt][nt][1] + xv.y + bv0;
                *(float2*)(out + base0 + nt * 8) = o;
                xv = *(const float2*)(x + base1 + nt * 8);
                o.x = acc[mt][nt][2] + xv.x + bv1;
                o.y = acc[mt][nt][3] + xv.y + bv1;
                *(float2*)(out + base1 + nt * 8) = o;
            }
        }
    }
}

// ================= launch =================
extern "C" void kernel_launch(void* const* d_in, const int* in_sizes, int n_in,
                              void* d_out, int out_size) {
    const float* x       = (const float*)d_in[0];
    const float* g_w     = (const float*)d_in[1];
    const float* g_b     = (const float*)d_in[2];
    const float* theta_w = (const float*)d_in[3];
    const float* theta_b = (const float*)d_in[4];
    const float* phi_w   = (const float*)d_in[5];
    const float* phi_b   = (const float*)d_in[6];
    const float* W_w     = (const float*)d_in[7];
    const float* W_b     = (const float*)d_in[8];
    float* out = (float*)d_out;

    int smem1 = 32768;
    int smem2 = 98304 + 1024;
    cudaFuncSetAttribute(pass1_kernel, cudaFuncAttributeMaxDynamicSharedMemorySize, smem1);
    cudaFuncSetAttribute(pass2_kernel, cudaFuncAttributeMaxDynamicSharedMemorySize, smem2);

    gwt_kernel<<<dim3(4, 8), 256>>>(g_w);
    pass1_kernel<<<dim3(3, NCH1, NB), 256, smem1>>>(x);
    reduce_kernel<<<96, 256>>>();
    fixup_kernel<<<dim3(65, NB), 256>>>();
    stageA_kernel<<<dim3(CI_ + 1, NB), 256>>>(phi_w, g_w);
    stageB_kernel<<<dim3(CI_, NB), 256>>>(g_b, phi_b);
    stageC_kernel<<<dim3(C_, NB), 256>>>(W_w);
    stageD_kernel<<<dim3(C_, NB), 256>>>(theta_w, theta_b, W_b);
    pass2_kernel<<<(UNITS + TPC - 1) / TPC, 256, smem2>>>(x, out);
}

// round 10
// speedup vs baseline: 3.5377x; 1.0438x over previous
#include <cuda_runtime.h>
#include <cuda_bf16.h>
#include <cuda_fp16.h>
#include <cstdint>
#include <cstddef>

#define NB 2
#define C_ 256
#define CI_ 128
#define NNPOS 65536
#define NCH1 49            // uneven k-chunks, pass1: 3 quads x 49 x 2 b = 294 CTAs
#define NT2 64             // spatial cols per pass2 tile
#define UNITS 4096         // NB * 2 mhalves * 1024 ntiles
#define TPC 14             // units per CTA pass2 -> 293 CTAs (occ 2)
#define CHAIN_BLOCKS 258

// ---------------- scratch (static device globals; no allocation) ----------------
__device__ __align__(16) float    d_Sp[(size_t)NB * NCH1 * 3 * 16384]; // partial S
__device__ __align__(16) float    d_sps[NB * NCH1 * C_];
__device__ __align__(16) float    d_S[NB * C_ * C_];
__device__ __align__(16) float    d_s[NB * C_];
__device__ __align__(16) float    d_gwT[C_ * CI_];        // g_w transposed [d][j]
__device__ __align__(16) float    d_T1[NB * CI_ * C_];
__device__ __align__(16) float    d_u[NB * CI_];
__device__ __align__(16) float    d_v[NB * CI_];
__device__ __align__(16) float    d_kvT[NB * CI_ * CI_];  // kv transposed [b][j][i]
__device__ __align__(16) float    d_b2[NB * C_];
__device__ __align__(16) uint32_t d_Ah16[NB * C_ * CI_];  // A fp16x2 [b][m][kpair]
__device__ unsigned d_cnt = 0;
__device__ unsigned d_gen = 0;

// ---------------- primitives ----------------
__device__ __forceinline__ uint32_t smem_u32(const void* p) {
    uint32_t a;
    asm("{ .reg .u64 t; cvta.to.shared.u64 t, %1; cvt.u32.u64 %0, t; }" : "=r"(a) : "l"(p));
    return a;
}
__device__ __forceinline__ void mma16816h(float* d, const uint32_t* a, const uint32_t* b) {
    asm volatile("mma.sync.aligned.m16n8k16.row.col.f32.f16.f16.f32 "
                 "{%0,%1,%2,%3}, {%4,%5,%6,%7}, {%8,%9}, {%0,%1,%2,%3};"
                 : "+f"(d[0]), "+f"(d[1]), "+f"(d[2]), "+f"(d[3])
                 : "r"(a[0]), "r"(a[1]), "r"(a[2]), "r"(a[3]), "r"(b[0]), "r"(b[1]));
}
__device__ __forceinline__ void ldsm4(uint32_t* r, uint32_t addr) {
    asm volatile("ldmatrix.sync.aligned.m8n8.x4.shared.b16 {%0,%1,%2,%3}, [%4];"
                 : "=r"(r[0]), "=r"(r[1]), "=r"(r[2]), "=r"(r[3]) : "r"(addr));
}
__device__ __forceinline__ void ldsm4t(uint32_t* r, uint32_t addr) {
    asm volatile("ldmatrix.sync.aligned.m8n8.x4.trans.shared.b16 {%0,%1,%2,%3}, [%4];"
                 : "=r"(r[0]), "=r"(r[1]), "=r"(r[2]), "=r"(r[3]) : "r"(addr));
}
__device__ __forceinline__ uint32_t sw128(uint32_t byte) { return byte ^ ((byte >> 3) & 0x70u); }
__device__ __forceinline__ uint32_t sw512(uint32_t byte) { return byte ^ ((byte >> 5) & 0x70u); }

__device__ __forceinline__ uint32_t packh(float x, float y) {
    __half2 h = __floats2half2_rn(x, y);
    return *(uint32_t*)&h;
}
__device__ __forceinline__ float4 f4fma(float s, float4 q, float4 a) {
    a.x += s * q.x; a.y += s * q.y; a.z += s * q.z; a.w += s * q.w;
    return a;
}

// grid-wide barrier (sense via monotonically increasing generation; replay-safe)
__device__ __forceinline__ void gridbar() {
    __syncthreads();
    if (threadIdx.x == 0) {
        __threadfence();
        unsigned g = *(volatile unsigned*)&d_gen;
        unsigned old = atomicAdd(&d_cnt, 1);
        if (old == CHAIN_BLOCKS - 1) {
            d_cnt = 0;
            __threadfence();
            atomicAdd(&d_gen, 1);
        } else {
            while (*(volatile unsigned*)&d_gen == g) { }
        }
        __threadfence();
    }
    __syncthreads();
}

extern __shared__ uint8_t dsm[];

// ================= pass 1: 3-quadrant syrk (fp16), partial S + rowsums ==========
__global__ __launch_bounds__(256, 2) void pass1_kernel(const float* __restrict__ x) {
    uint8_t* Ah = dsm;            // 128 x 64 fp16 sw128, 16KB each
    uint8_t* Bh = dsm + 16384;

    int qi = blockIdx.x, ch = blockIdx.y, b = blockIdx.z;
    int qm = qi >> 1, qn = (qi + 1) >> 1;   // 0:(0,0) 1:(0,1) 2:(1,1)
    bool diag = (qi != 1);
    int kt0 = (ch * 1024) / NCH1, kt1 = ((ch + 1) * 1024) / NCH1;
    const float* xa = x + ((size_t)(b * C_ + qm * 128)) * NNPOS;
    const float* xb = x + ((size_t)(b * C_ + qn * 128)) * NNPOS;

    int t = threadIdx.x, w = t >> 5, lane = t & 31;
    int lrow = t >> 1, lhalf = t & 1;
    int wm = w >> 1, wn = w & 1;
    int m0 = wm * 32, n0 = wn * 64;

    uint32_t ahb = smem_u32(Ah);
    uint32_t bhb = diag ? ahb : smem_u32(Bh);

    float acc[2][8][4];
#pragma unroll
    for (int i = 0; i < 2; i++)
#pragma unroll
        for (int j = 0; j < 8; j++)
#pragma unroll
            for (int q = 0; q < 4; q++) acc[i][j][q] = 0.f;

    float rs = 0.f;

    for (int kt = kt0; kt < kt1; kt++) {
        {
            const float* pa = xa + (size_t)lrow * NNPOS + kt * 64 + lhalf * 32;
#pragma unroll
            for (int i = 0; i < 8; i++) {
                float4 v = *(const float4*)(pa + i * 4);
                if (diag) rs += v.x + v.y + v.z + v.w;
                uint32_t byte = (uint32_t)lrow * 128u + (uint32_t)(lhalf * 32 + i * 4) * 2u;
                *(uint2*)(Ah + sw128(byte)) = make_uint2(packh(v.x, v.y), packh(v.z, v.w));
            }
            if (!diag) {
                const float* pb = xb + (size_t)lrow * NNPOS + kt * 64 + lhalf * 32;
#pragma unroll
                for (int i = 0; i < 8; i++) {
                    float4 v = *(const float4*)(pb + i * 4);
                    uint32_t byte = (uint32_t)lrow * 128u + (uint32_t)(lhalf * 32 + i * 4) * 2u;
                    *(uint2*)(Bh + sw128(byte)) = make_uint2(packh(v.x, v.y), packh(v.z, v.w));
                }
            }
        }
        __syncthreads();
#pragma unroll
        for (int ks = 0; ks < 4; ks++) {
            int k0 = ks * 16;
            uint32_t ah[2][4];
#pragma unroll
            for (int mt = 0; mt < 2; mt++) {
                uint32_t byte = (uint32_t)(m0 + mt * 16 + (lane & 15)) * 128u
                              + (uint32_t)(k0 + (lane >> 4) * 8) * 2u;
                ldsm4(ah[mt], ahb + sw128(byte));
            }
            uint32_t bf[8][2];
            int g = lane >> 3, j = lane & 7;
#pragma unroll
            for (int n2 = 0; n2 < 4; n2++) {
                uint32_t row = (uint32_t)(n0 + n2 * 16 + (g >> 1) * 8 + j);
                uint32_t kk  = (uint32_t)(k0 + (g & 1) * 8);
                uint32_t r[4];
                ldsm4(r, bhb + sw128(row * 128u + kk * 2u));
                bf[n2 * 2][0] = r[0]; bf[n2 * 2][1] = r[1];
                bf[n2 * 2 + 1][0] = r[2]; bf[n2 * 2 + 1][1] = r[3];
            }
#pragma unroll
            for (int mt = 0; mt < 2; mt++)
#pragma unroll
                for (int nt = 0; nt < 8; nt++)
                    mma16816h(acc[mt][nt], ah[mt], bf[nt]);
        }
        __syncthreads();
    }

    float* Sp = d_Sp + (((size_t)(b * NCH1 + ch) * 3 + qi) << 14);
#pragma unroll
    for (int mt = 0; mt < 2; mt++) {
        int r = m0 + mt * 16 + (lane >> 2);
        int c = n0 + 2 * (lane & 3);
#pragma unroll
        for (int nt = 0; nt < 8; nt++) {
            *(float2*)(Sp + (size_t)r * 128 + c + nt * 8)
                = make_float2(acc[mt][nt][0], acc[mt][nt][1]);
            *(float2*)(Sp + (size_t)(r + 8) * 128 + c + nt * 8)
                = make_float2(acc[mt][nt][2], acc[mt][nt][3]);
        }
    }
    if (diag) {
        rs += __shfl_xor_sync(0xFFFFFFFFu, rs, 1);
        if (lhalf == 0)
            d_sps[(b * NCH1 + ch) * C_ + qm * 128 + lrow] = rs;
    }
}

// ================= chain: reduce+mirror+rowsum+gwt | stageA | stageB | stageC+D ===
__global__ __launch_bounds__(256, 2) void chain_kernel(
    const float* __restrict__ g_w, const float* __restrict__ phi_w,
    const float* __restrict__ g_b, const float* __restrict__ phi_b,
    const float* __restrict__ W_w, const float* __restrict__ theta_w,
    const float* __restrict__ theta_b, const float* __restrict__ W_b) {
    __shared__ __align__(16) uint8_t shraw[8448];
    int bx = blockIdx.x, t = threadIdx.x;

    // ---------- phase 1: reduce partial S (+mirror), gwt transpose, rowsums ------
    if (bx < 96) {
        int id = bx * 256 + t;
        int b = id / 12288, rest = id % 12288;
        int slot = rest >> 12, idx4 = rest & 4095;
        const float4* p = (const float4*)d_Sp;
        size_t base = ((size_t)b * NCH1 * 3 + slot) * 4096 + idx4;
        float4 a = make_float4(0.f, 0.f, 0.f, 0.f);
#pragma unroll 7
        for (int ch = 0; ch < NCH1; ch++) {
            float4 v = p[base + (size_t)ch * 3 * 4096];
            a.x += v.x; a.y += v.y; a.z += v.z; a.w += v.w;
        }
        int ml = idx4 >> 5, c4 = idx4 & 31;
        int m = (slot == 2) ? 128 + ml : ml;
        int n4 = (slot == 0) ? c4 : 32 + c4;
        ((float4*)d_S)[(size_t)b * 16384 + m * 64 + n4] = a;
        if (slot == 1) {                       // mirror quad(1,0) = quad(0,1)^T
            float* Sb = d_S + (size_t)b * 65536;
            int nb = 128 + c4 * 4;
            Sb[(size_t)(nb + 0) * 256 + ml] = a.x;
            Sb[(size_t)(nb + 1) * 256 + ml] = a.y;
            Sb[(size_t)(nb + 2) * 256 + ml] = a.z;
            Sb[(size_t)(nb + 3) * 256 + ml] = a.w;
        }
    } else if (bx < 128) {                     // gwt: transpose g_w -> d_gwT
        float (*tile)[33] = (float (*)[33])shraw;
        int tb = bx - 96;
        int rt = tb >> 3, ct = tb & 7;
        int ty = t >> 5, tx = t & 31;
#pragma unroll
        for (int p = 0; p < 4; p++)
            tile[p * 8 + ty][tx] = g_w[(rt * 32 + p * 8 + ty) * C_ + ct * 32 + tx];
        __syncthreads();
#pragma unroll
        for (int p = 0; p < 4; p++)
            d_gwT[(ct * 32 + p * 8 + ty) * CI_ + rt * 32 + tx] = tile[tx][p * 8 + ty];
    } else if (bx < 130) {                     // rowsums
        int b = bx - 128;
        float acc = 0.f;
#pragma unroll 7
        for (int ch = 0; ch < NCH1; ch++) acc += d_sps[(b * NCH1 + ch) * C_ + t];
        d_s[b * C_ + t] = acc;
    }
    gridbar();

    // ---------- phase 2: stageA (T1 = phi_w @ S ; u,v) ---------------------------
    {
        int i = bx >> 1, b = bx & 1;
        if (i < CI_) {
            float* ph = (float*)shraw;                       // 256 floats
            float4 (*red)[64] = (float4 (*)[64])(shraw + 1024);
            ph[t] = phi_w[i * C_ + t];
            __syncthreads();
            int kq = t >> 6, jv = t & 63;
            const float4* S4 = (const float4*)(d_S + (size_t)b * 65536);
            float4 a = make_float4(0.f, 0.f, 0.f, 0.f);
#pragma unroll 8
            for (int c = kq * 64; c < kq * 64 + 64; c++)
                a = f4fma(ph[c], S4[c * 64 + jv], a);
            red[kq][jv] = a;
            __syncthreads();
            if (kq == 0) {
                float4 s0 = red[0][jv], s1 = red[1][jv], s2 = red[2][jv], s3 = red[3][jv];
                float4 o;
                o.x = s0.x + s1.x + s2.x + s3.x; o.y = s0.y + s1.y + s2.y + s3.y;
                o.z = s0.z + s1.z + s2.z + s3.z; o.w = s0.w + s1.w + s2.w + s3.w;
                ((float4*)(d_T1 + ((size_t)b * CI_ + i) * C_))[jv] = o;
            }
        } else if (i == CI_) {
            float* ss = (float*)shraw;
            ss[t] = d_s[b * C_ + t];
            __syncthreads();
            int hf = t >> 7, ii = t & 127;
            const float4* wr = (const float4*)((hf ? g_w : phi_w) + ii * C_);
            const float4* sv = (const float4*)ss;
            float acc = 0.f;
#pragma unroll 8
            for (int q = 0; q < 64; q++) {
                float4 wv = wr[q], s4 = sv[q];
                acc += wv.x * s4.x + wv.y * s4.y + wv.z * s4.z + wv.w * s4.w;
            }
            if (hf) d_v[b * CI_ + ii] = acc; else d_u[b * CI_ + ii] = acc;
        }
    }
    gridbar();

    // ---------- phase 3: stageB (kvT) --------------------------------------------
    if (bx < 256) {
        int i = bx >> 1, b = bx & 1;
        float* t1 = (float*)shraw;                           // 256 floats
        float4 (*red)[32] = (float4 (*)[32])(shraw + 1024);  // 8x32 f4
        t1[t] = d_T1[((size_t)b * CI_ + i) * C_ + t];
        __syncthreads();
        int kq = t >> 5, jv = t & 31;
        const float4* Q = (const float4*)d_gwT;
        float4 a = make_float4(0.f, 0.f, 0.f, 0.f);
#pragma unroll 8
        for (int d = kq * 32; d < kq * 32 + 32; d++)
            a = f4fma(t1[d], Q[d * 32 + jv], a);
        red[kq][jv] = a;
        __syncthreads();
        if (kq == 0) {
            float4 o = make_float4(0.f, 0.f, 0.f, 0.f);
#pragma unroll
            for (int q = 0; q < 8; q++) {
                float4 v = red[q][jv];
                o.x += v.x; o.y += v.y; o.z += v.z; o.w += v.w;
            }
            float ui = d_u[b * CI_ + i], pb = phi_b[i];
            float4 gb = ((const float4*)g_b)[jv];
            float4 vv = ((const float4*)(d_v + b * CI_))[jv];
            o.x += ui * gb.x + pb * vv.x + 65536.0f * pb * gb.x;
            o.y += ui * gb.y + pb * vv.y + 65536.0f * pb * gb.y;
            o.z += ui * gb.z + pb * vv.z + 65536.0f * pb * gb.z;
            o.w += ui * gb.w + pb * vv.w + 65536.0f * pb * gb.w;
            float* kt = d_kvT + (size_t)b * CI_ * CI_;
            kt[(jv * 4 + 0) * CI_ + i] = o.x;
            kt[(jv * 4 + 1) * CI_ + i] = o.y;
            kt[(jv * 4 + 2) * CI_ + i] = o.z;
            kt[(jv * 4 + 3) * CI_ + i] = o.w;
        }
    }
    gridbar();

    // ---------- phase 4: stageC+D fused (per m-row) ------------------------------
    if (bx < 256) {
        int m = bx;
        float*  ww   = (float*)shraw;                         // 128
        float4 (*red)[32] = (float4 (*)[32])(shraw + 512);    // 8x32 f4 (4KB)
        float*  mmv  = (float*)(shraw + 4608);                // 128
        float*  bred = (float*)(shraw + 5120);                // 128
        float4 (*redD)[64] = (float4 (*)[64])(shraw + 512);   // reuse 4KB for D
        for (int b = 0; b < NB; b++) {
            // C: M[m][i] = (1/N) W_w[m]·kvT[:,i]
            if (t < CI_) ww[t] = W_w[m * CI_ + t];
            __syncthreads();
            int kq = t >> 5, iv = t & 31;
            const float4* Q = (const float4*)(d_kvT + (size_t)b * CI_ * CI_);
            float4 a = make_float4(0.f, 0.f, 0.f, 0.f);
#pragma unroll 8
            for (int j = kq * 16; j < kq * 16 + 16; j++)
                a = f4fma(ww[j], Q[j * 32 + iv], a);
            red[kq][iv] = a;
            __syncthreads();
            if (kq == 0) {
                float4 o = make_float4(0.f, 0.f, 0.f, 0.f);
#pragma unroll
                for (int q = 0; q < 8; q++) {
                    float4 v = red[q][iv];
                    o.x += v.x; o.y += v.y; o.z += v.z; o.w += v.w;
                }
                const float inv = 1.0f / 65536.0f;
                mmv[iv * 4 + 0] = o.x * inv;
                mmv[iv * 4 + 1] = o.y * inv;
                mmv[iv * 4 + 2] = o.z * inv;
                mmv[iv * 4 + 3] = o.w * inv;
            }
            __syncthreads();
            // D: A row -> fp16 ; b2
            int kq2 = t >> 6, jv2 = t & 63;
            const float4* Qt = (const float4*)theta_w;
            float4 ad = make_float4(0.f, 0.f, 0.f, 0.f);
#pragma unroll 8
            for (int i = kq2 * 32; i < kq2 * 32 + 32; i++)
                ad = f4fma(mmv[i], Qt[i * 64 + jv2], ad);
            redD[kq2][jv2] = ad;
            if (t < CI_) bred[t] = mmv[t] * theta_b[t];
            __syncthreads();
            if (kq2 == 0) {
                float4 s0 = redD[0][jv2], s1 = redD[1][jv2], s2 = redD[2][jv2], s3 = redD[3][jv2];
                float a0 = s0.x + s1.x + s2.x + s3.x, a1 = s0.y + s1.y + s2.y + s3.y;
                float a2 = s0.z + s1.z + s2.z + s3.z, a3 = s0.w + s1.w + s2.w + s3.w;
                size_t base = ((size_t)b * C_ + m) * CI_ + jv2 * 2;
                d_Ah16[base]     = packh(a0, a1);
                d_Ah16[base + 1] = packh(a2, a3);
            }
            for (int s2v = 64; s2v > 0; s2v >>= 1) {
                if (t < s2v) bred[t] += bred[t + s2v];
                __syncthreads();
            }
            if (t == 0) d_b2[b * C_ + m] = bred[0] + W_b[m];
            __syncthreads();
        }
    }
}

// ================= pass 2: out = x + A x + b2 (fp16, m-half per CTA, occ 2) ======
__global__ __launch_bounds__(256, 2) void pass2_kernel(const float* __restrict__ x,
                                                       float* __restrict__ out) {
    int start = blockIdx.x * TPC;
    int end = start + TPC; if (end > UNITS) end = UNITS;
    if (start >= UNITS) return;

    uint8_t* Ahs = dsm;
    uint8_t* Xhs = dsm + 65536;
    float*   b2s = (float*)(dsm + 98304);
    uint32_t ahb = smem_u32(Ahs), xhb = smem_u32(Xhs);

    int t = threadIdx.x, w = t >> 5, lane = t & 31;
    int m0 = (w >> 1) * 32;
    int n0w = (w & 1) * 32;
    int prow = t >> 2, pq = t & 3;

    uint32_t Rh[32];
    auto prefetch = [&](int u) {
        int bg = u >> 11, n02 = (u & 1023) * NT2;
#pragma unroll
        for (int p = 0; p < 4; p++) {
            const float* src = x + ((size_t)(bg * C_ + prow + p * 64)) * NNPOS + n02 + pq * 16;
#pragma unroll
            for (int i = 0; i < 4; i++) {
                float4 v = *(const float4*)(src + i * 4);
                Rh[p * 8 + i * 2]     = packh(v.x, v.y);
                Rh[p * 8 + i * 2 + 1] = packh(v.z, v.w);
            }
        }
    };

    prefetch(start);
    int cur = -1;
    for (int it = 0; it < end - start; it++) {
        int u = start + it;
        int bg = u >> 11, mh = (u >> 10) & 1, n0t = (u & 1023) * NT2;

        __syncthreads();
        if ((u >> 10) != cur) {
            const uint4* Ah4 = (const uint4*)(d_Ah16 + ((size_t)(bg * C_ + mh * 128)) * CI_);
#pragma unroll
            for (int ii = 0; ii < 16; ii++) {
                int idx = ii * 256 + t;
                uint32_t byte = (uint32_t)(idx >> 5) * 512u + (uint32_t)(idx & 31) * 16u;
                *(uint4*)(Ahs + sw512(byte)) = Ah4[idx];
            }
            if (t < 128) b2s[t] = d_b2[bg * C_ + mh * 128 + t];
            cur = u >> 10;
        }
#pragma unroll
        for (int p = 0; p < 4; p++) {
            uint32_t rowb = (uint32_t)(prow + p * 64) * 128u;
#pragma unroll
            for (int i = 0; i < 4; i++) {
                uint32_t sw = sw128(rowb + (uint32_t)(pq * 16 + i * 4) * 2u);
                *(uint2*)(Xhs + sw) = make_uint2(Rh[p * 8 + i * 2], Rh[p * 8 + i * 2 + 1]);
            }
        }
        __syncthreads();
        if (it + 1 < end - start) prefetch(u + 1);    // overlaps mma below

        float acc[2][4][4];
#pragma unroll
        for (int i = 0; i < 2; i++)
#pragma unroll
            for (int j = 0; j < 4; j++)
#pragma unroll
                for (int q = 0; q < 4; q++) acc[i][j][q] = 0.f;

#pragma unroll 4
        for (int ks = 0; ks < 16; ks++) {
            int k0 = ks * 16;
            uint32_t ah[2][4];
#pragma unroll
            for (int mt = 0; mt < 2; mt++) {
                uint32_t byte = (uint32_t)(m0 + mt * 16 + (lane & 15)) * 512u
                              + (uint32_t)(k0 + (lane >> 4) * 8) * 2u;
                ldsm4(ah[mt], ahb + sw512(byte));
            }
            uint32_t bf[4][2];
            int g = lane >> 3, j = lane & 7;
#pragma unroll
            for (int n2 = 0; n2 < 2; n2++) {
                uint32_t rowk = (uint32_t)(k0 + (g & 1) * 8 + j);
                uint32_t coln = (uint32_t)(n0w + n2 * 16 + (g >> 1) * 8);
                uint32_t r[4];
                ldsm4t(r, xhb + sw128(rowk * 128u + coln * 2u));
                bf[n2 * 2][0] = r[0]; bf[n2 * 2][1] = r[1];
                bf[n2 * 2 + 1][0] = r[2]; bf[n2 * 2 + 1][1] = r[3];
            }
#pragma unroll
            for (int mt = 0; mt < 2; mt++)
#pragma unroll
                for (int nt = 0; nt < 4; nt++)
                    mma16816h(acc[mt][nt], ah[mt], bf[nt]);
        }

        // epilogue: out = acc + x + b2 (fp32 residual; x rows L2-hot)
#pragma unroll
        for (int mt = 0; mt < 2; mt++) {
            int r = m0 + mt * 16 + (lane >> 2);
            float bv0 = b2s[r], bv1 = b2s[r + 8];
            size_t base0 = ((size_t)(bg * C_ + mh * 128 + r)) * NNPOS + n0t + n0w + 2 * (lane & 3);
            size_t base1 = base0 + (size_t)8 * NNPOS;
#pragma unroll
            for (int nt = 0; nt < 4; nt++) {
                float2 xv = *(const float2*)(x + base0 + nt * 8);
                float2 o;
                o.x = acc[mt][nt][0] + xv.x + bv0;
                o.y = acc[mt][nt][1] + xv.y + bv0;
                *(float2*)(out + base0 + nt * 8) = o;
                xv = *(const float2*)(x + base1 + nt * 8);
                o.x = acc[mt][nt][2] + xv.x + bv1;
                o.y = acc[mt][nt][3] + xv.y + bv1;
                *(float2*)(out + base1 + nt * 8) = o;
            }
        }
    }
}

// ================= launch =================
extern "C" void kernel_launch(void* const* d_in, const int* in_sizes, int n_in,
                              void* d_out, int out_size) {
    const float* x       = (const float*)d_in[0];
    const float* g_w     = (const float*)d_in[1];
    const float* g_b     = (const float*)d_in[2];
    const float* theta_w = (const float*)d_in[3];
    const float* theta_b = (const float*)d_in[4];
    const float* phi_w   = (const float*)d_in[5];
    const float* phi_b   = (const float*)d_in[6];
    const float* W_w     = (const float*)d_in[7];
    const float* W_b     = (const float*)d_in[8];
    float* out = (float*)d_out;

    int smem1 = 32768;
    int smem2 = 98304 + 1024;
    cudaFuncSetAttribute(pass1_kernel, cudaFuncAttributeMaxDynamicSharedMemorySize, smem1);
    cudaFuncSetAttribute(pass2_kernel, cudaFuncAttributeMaxDynamicSharedMemorySize, smem2);

    pass1_kernel<<<dim3(3, NCH1, NB), 256, smem1>>>(x);
    chain_kernel<<<CHAIN_BLOCKS, 256>>>(g_w, phi_w, g_b, phi_b, W_w, theta_w, theta_b, W_b);
    pass2_kernel<<<(UNITS + TPC - 1) / TPC, 256, smem2>>>(x, out);
}

// round 11
// speedup vs baseline: 5.2679x; 1.4891x over previous
#include <cuda_runtime.h>
#include <cuda_bf16.h>
#include <cuda_fp16.h>
#include <cstdint>
#include <cstddef>

#define NB 2
#define C_ 256
#define CI_ 128
#define NNPOS 65536
#define NCH1 49            // uneven k-chunks, pass1: 3 quads x 49 x 2 b = 294 CTAs
#define NT2 64             // spatial cols per pass2 tile
#define UNITS 4096         // NB * 2 mhalves * 1024 ntiles
#define TPC 28             // units per CTA pass2 -> 147 CTAs (occ 1, one wave)
#define CHAIN_BLOCKS 258

// ---------------- scratch (static device globals; no allocation) ----------------
__device__ __align__(16) __half   d_xh[(size_t)NB * C_ * NNPOS];       // x in fp16 (67MB)
__device__ __align__(16) float    d_Sp[(size_t)NB * NCH1 * 3 * 16384]; // partial S
__device__ __align__(16) float    d_S[NB * C_ * C_];
__device__ __align__(16) float    d_s[NB * C_];
__device__ __align__(16) float    d_gwT[C_ * CI_];        // g_w transposed [d][j]
__device__ __align__(16) float    d_T1[NB * CI_ * C_];
__device__ __align__(16) float    d_u[NB * CI_];
__device__ __align__(16) float    d_v[NB * CI_];
__device__ __align__(16) float    d_kvT[NB * CI_ * CI_];  // kv transposed [b][j][i]
__device__ __align__(16) float    d_b2[NB * C_];
__device__ __align__(16) uint32_t d_Ah16[NB * C_ * CI_];  // A fp16x2 [b][m][kpair]
__device__ unsigned d_cnt = 0;
__device__ unsigned d_gen = 0;

// ---------------- primitives ----------------
__device__ __forceinline__ uint32_t smem_u32(const void* p) {
    uint32_t a;
    asm("{ .reg .u64 t; cvta.to.shared.u64 t, %1; cvt.u32.u64 %0, t; }" : "=r"(a) : "l"(p));
    return a;
}
__device__ __forceinline__ void mma16816h(float* d, const uint32_t* a, const uint32_t* b) {
    asm volatile("mma.sync.aligned.m16n8k16.row.col.f32.f16.f16.f32 "
                 "{%0,%1,%2,%3}, {%4,%5,%6,%7}, {%8,%9}, {%0,%1,%2,%3};"
                 : "+f"(d[0]), "+f"(d[1]), "+f"(d[2]), "+f"(d[3])
                 : "r"(a[0]), "r"(a[1]), "r"(a[2]), "r"(a[3]), "r"(b[0]), "r"(b[1]));
}
__device__ __forceinline__ void ldsm4(uint32_t* r, uint32_t addr) {
    asm volatile("ldmatrix.sync.aligned.m8n8.x4.shared.b16 {%0,%1,%2,%3}, [%4];"
                 : "=r"(r[0]), "=r"(r[1]), "=r"(r[2]), "=r"(r[3]) : "r"(addr));
}
__device__ __forceinline__ void ldsm4t(uint32_t* r, uint32_t addr) {
    asm volatile("ldmatrix.sync.aligned.m8n8.x4.trans.shared.b16 {%0,%1,%2,%3}, [%4];"
                 : "=r"(r[0]), "=r"(r[1]), "=r"(r[2]), "=r"(r[3]) : "r"(addr));
}
__device__ __forceinline__ uint32_t sw128(uint32_t byte) { return byte ^ ((byte >> 3) & 0x70u); }
__device__ __forceinline__ uint32_t sw512(uint32_t byte) { return byte ^ ((byte >> 5) & 0x70u); }

__device__ __forceinline__ uint32_t packh(float x, float y) {
    __half2 h = __floats2half2_rn(x, y);
    return *(uint32_t*)&h;
}
__device__ __forceinline__ float4 f4fma(float s, float4 q, float4 a) {
    a.x += s * q.x; a.y += s * q.y; a.z += s * q.z; a.w += s * q.w;
    return a;
}
__device__ __forceinline__ void cpasync16(uint32_t dst, const void* src) {
    asm volatile("cp.async.cg.shared.global [%0], [%1], 16;" :: "r"(dst), "l"(src));
}
#define CP_COMMIT() asm volatile("cp.async.commit_group;" ::: "memory")
#define CP_WAIT2()  asm volatile("cp.async.wait_group 2;" ::: "memory")

// grid-wide barrier (sense via monotonically increasing generation; replay-safe)
__device__ __forceinline__ void gridbar() {
    __syncthreads();
    if (threadIdx.x == 0) {
        __threadfence();
        unsigned g = *(volatile unsigned*)&d_gen;
        unsigned old = atomicAdd(&d_cnt, 1);
        if (old == CHAIN_BLOCKS - 1) {
            d_cnt = 0;
            __threadfence();
            atomicAdd(&d_gen, 1);
        } else {
            while (*(volatile unsigned*)&d_gen == g) { }
        }
        __threadfence();
    }
    __syncthreads();
}

extern __shared__ uint8_t dsm[];

// ================= prepass: x -> fp16 xh, rowsums =================
__global__ __launch_bounds__(256) void prepass_kernel(const float* __restrict__ x) {
    int row = blockIdx.x;                 // 0..511 = b*C_+c
    const float4* src = (const float4*)(x + (size_t)row * NNPOS);
    uint2* dst = (uint2*)(d_xh + (size_t)row * NNPOS);
    int t = threadIdx.x;
    float rs = 0.f;
#pragma unroll 4
    for (int i = t; i < NNPOS / 4; i += 256) {
        float4 v = src[i];
        rs += v.x + v.y + v.z + v.w;
        dst[i] = make_uint2(packh(v.x, v.y), packh(v.z, v.w));
    }
    __shared__ float red[256];
    red[t] = rs;
    __syncthreads();
    for (int s = 128; s > 0; s >>= 1) {
        if (t < s) red[t] += red[t + s];
        __syncthreads();
    }
    if (t == 0) d_s[row] = red[0];
}

// ================= pass 1: 3-quadrant syrk, cp.async 3-stage pipeline ============
// grid (3, NCH1, NB), block 256; smem = 3 stages x 32KB (A 16KB | B 16KB)
__global__ __launch_bounds__(256, 2) void pass1_kernel() {
    int qi = blockIdx.x, ch = blockIdx.y, b = blockIdx.z;
    int qm = qi >> 1, qn = (qi + 1) >> 1;   // 0:(0,0) 1:(0,1) 2:(1,1)
    bool diag = (qi != 1);
    int kt0 = (ch * 1024) / NCH1, kt1 = ((ch + 1) * 1024) / NCH1;
    const __half* xa = d_xh + ((size_t)(b * C_ + qm * 128)) * NNPOS;
    const __half* xb = d_xh + ((size_t)(b * C_ + qn * 128)) * NNPOS;

    int t = threadIdx.x, w = t >> 5, lane = t & 31;
    int wm = w >> 1, wn = w & 1;
    int m0 = wm * 32, n0 = wn * 64;
    uint32_t sbase = smem_u32(dsm);

    float acc[2][8][4];
#pragma unroll
    for (int i = 0; i < 2; i++)
#pragma unroll
        for (int j = 0; j < 8; j++)
#pragma unroll
            for (int q = 0; q < 4; q++) acc[i][j][q] = 0.f;

    auto load_tile = [&](int kt, int s) {
        uint32_t stA = sbase + (uint32_t)s * 32768u;
#pragma unroll
        for (int i = 0; i < 4; i++) {
            int c = i * 256 + t;
            int row = c >> 3, col16 = c & 7;
            cpasync16(stA + sw128((uint32_t)row * 128u + (uint32_t)col16 * 16u),
                      xa + (size_t)row * NNPOS + kt * 64 + col16 * 8);
        }
        if (!diag) {
            uint32_t stB = stA + 16384u;
#pragma unroll
            for (int i = 0; i < 4; i++) {
                int c = i * 256 + t;
                int row = c >> 3, col16 = c & 7;
                cpasync16(stB + sw128((uint32_t)row * 128u + (uint32_t)col16 * 16u),
                          xb + (size_t)row * NNPOS + kt * 64 + col16 * 8);
            }
        }
    };

    int nkt = kt1 - kt0;
    load_tile(kt0, 0); CP_COMMIT();
    if (nkt > 1) load_tile(kt0 + 1, 1);
    CP_COMMIT();

    for (int i = 0; i < nkt; i++) {
        if (i + 2 < nkt) load_tile(kt0 + i + 2, (i + 2) % 3);
        CP_COMMIT();                       // always one group per iter (may be empty)
        CP_WAIT2();                        // tile i resident
        __syncthreads();
        uint32_t ahb = sbase + (uint32_t)(i % 3) * 32768u;
        uint32_t bhb = diag ? ahb : ahb + 16384u;
#pragma unroll
        for (int ks = 0; ks < 4; ks++) {
            int k0 = ks * 16;
            uint32_t ah[2][4];
#pragma unroll
            for (int mt = 0; mt < 2; mt++) {
                uint32_t byte = (uint32_t)(m0 + mt * 16 + (lane & 15)) * 128u
                              + (uint32_t)(k0 + (lane >> 4) * 8) * 2u;
                ldsm4(ah[mt], ahb + sw128(byte));
            }
            uint32_t bf[8][2];
            int g = lane >> 3, j = lane & 7;
#pragma unroll
            for (int n2 = 0; n2 < 4; n2++) {
                uint32_t row = (uint32_t)(n0 + n2 * 16 + (g >> 1) * 8 + j);
                uint32_t kk  = (uint32_t)(k0 + (g & 1) * 8);
                uint32_t r[4];
                ldsm4(r, bhb + sw128(row * 128u + kk * 2u));
                bf[n2 * 2][0] = r[0]; bf[n2 * 2][1] = r[1];
                bf[n2 * 2 + 1][0] = r[2]; bf[n2 * 2 + 1][1] = r[3];
            }
#pragma unroll
            for (int mt = 0; mt < 2; mt++)
#pragma unroll
                for (int nt = 0; nt < 8; nt++)
                    mma16816h(acc[mt][nt], ah[mt], bf[nt]);
        }
        __syncthreads();
    }

    float* Sp = d_Sp + (((size_t)(b * NCH1 + ch) * 3 + qi) << 14);
#pragma unroll
    for (int mt = 0; mt < 2; mt++) {
        int r = m0 + mt * 16 + (lane >> 2);
        int c = n0 + 2 * (lane & 3);
#pragma unroll
        for (int nt = 0; nt < 8; nt++) {
            *(float2*)(Sp + (size_t)r * 128 + c + nt * 8)
                = make_float2(acc[mt][nt][0], acc[mt][nt][1]);
            *(float2*)(Sp + (size_t)(r + 8) * 128 + c + nt * 8)
                = make_float2(acc[mt][nt][2], acc[mt][nt][3]);
        }
    }
}

// ================= chain: reduce+mirror+gwt | stageA | stageB | stageC+D =========
__global__ __launch_bounds__(256, 2) void chain_kernel(
    const float* __restrict__ g_w, const float* __restrict__ phi_w,
    const float* __restrict__ g_b, const float* __restrict__ phi_b,
    const float* __restrict__ W_w, const float* __restrict__ theta_w,
    const float* __restrict__ theta_b, const float* __restrict__ W_b) {
    __shared__ __align__(16) uint8_t shraw[8448];
    int bx = blockIdx.x, t = threadIdx.x;

    // ---------- phase 1: reduce partial S (+mirror), gwt transpose ---------------
    if (bx < 96) {
        int id = bx * 256 + t;
        int b = id / 12288, rest = id % 12288;
        int slot = rest >> 12, idx4 = rest & 4095;
        const float4* p = (const float4*)d_Sp;
        size_t base = ((size_t)b * NCH1 * 3 + slot) * 4096 + idx4;
        float4 a = make_float4(0.f, 0.f, 0.f, 0.f);
#pragma unroll 7
        for (int ch = 0; ch < NCH1; ch++) {
            float4 v = p[base + (size_t)ch * 3 * 4096];
            a.x += v.x; a.y += v.y; a.z += v.z; a.w += v.w;
        }
        int ml = idx4 >> 5, c4 = idx4 & 31;
        int m = (slot == 2) ? 128 + ml : ml;
        int n4 = (slot == 0) ? c4 : 32 + c4;
        ((float4*)d_S)[(size_t)b * 16384 + m * 64 + n4] = a;
        if (slot == 1) {                       // mirror quad(1,0) = quad(0,1)^T
            float* Sb = d_S + (size_t)b * 65536;
            int nb = 128 + c4 * 4;
            Sb[(size_t)(nb + 0) * 256 + ml] = a.x;
            Sb[(size_t)(nb + 1) * 256 + ml] = a.y;
            Sb[(size_t)(nb + 2) * 256 + ml] = a.z;
            Sb[(size_t)(nb + 3) * 256 + ml] = a.w;
        }
    } else if (bx < 128) {                     // gwt: transpose g_w -> d_gwT
        float (*tile)[33] = (float (*)[33])shraw;
        int tb = bx - 96;
        int rt = tb >> 3, ct = tb & 7;
        int ty = t >> 5, tx = t & 31;
#pragma unroll
        for (int p = 0; p < 4; p++)
            tile[p * 8 + ty][tx] = g_w[(rt * 32 + p * 8 + ty) * C_ + ct * 32 + tx];
        __syncthreads();
#pragma unroll
        for (int p = 0; p < 4; p++)
            d_gwT[(ct * 32 + p * 8 + ty) * CI_ + rt * 32 + tx] = tile[tx][p * 8 + ty];
    }
    gridbar();

    // ---------- phase 2: stageA (T1 = phi_w @ S ; u,v) ---------------------------
    {
        int i = bx >> 1, b = bx & 1;
        if (i < CI_) {
            float* ph = (float*)shraw;
            float4 (*red)[64] = (float4 (*)[64])(shraw + 1024);
            ph[t] = phi_w[i * C_ + t];
            __syncthreads();
            int kq = t >> 6, jv = t & 63;
            const float4* S4 = (const float4*)(d_S + (size_t)b * 65536);
            float4 a = make_float4(0.f, 0.f, 0.f, 0.f);
#pragma unroll 8
            for (int c = kq * 64; c < kq * 64 + 64; c++)
                a = f4fma(ph[c], S4[c * 64 + jv], a);
            red[kq][jv] = a;
            __syncthreads();
            if (kq == 0) {
                float4 s0 = red[0][jv], s1 = red[1][jv], s2 = red[2][jv], s3 = red[3][jv];
                float4 o;
                o.x = s0.x + s1.x + s2.x + s3.x; o.y = s0.y + s1.y + s2.y + s3.y;
                o.z = s0.z + s1.z + s2.z + s3.z; o.w = s0.w + s1.w + s2.w + s3.w;
                ((float4*)(d_T1 + ((size_t)b * CI_ + i) * C_))[jv] = o;
            }
        } else if (i == CI_) {
            float* ss = (float*)shraw;
            ss[t] = d_s[b * C_ + t];
            __syncthreads();
            int hf = t >> 7, ii = t & 127;
            const float4* wr = (const float4*)((hf ? g_w : phi_w) + ii * C_);
            const float4* sv = (const float4*)ss;
            float acc = 0.f;
#pragma unroll 8
            for (int q = 0; q < 64; q++) {
                float4 wv = wr[q], s4 = sv[q];
                acc += wv.x * s4.x + wv.y * s4.y + wv.z * s4.z + wv.w * s4.w;
            }
            if (hf) d_v[b * CI_ + ii] = acc; else d_u[b * CI_ + ii] = acc;
        }
    }
    gridbar();

    // ---------- phase 3: stageB (kvT) --------------------------------------------
    if (bx < 256) {
        int i = bx >> 1, b = bx & 1;
        float* t1 = (float*)shraw;
        float4 (*red)[32] = (float4 (*)[32])(shraw + 1024);
        t1[t] = d_T1[((size_t)b * CI_ + i) * C_ + t];
        __syncthreads();
        int kq = t >> 5, jv = t & 31;
        const float4* Q = (const float4*)d_gwT;
        float4 a = make_float4(0.f, 0.f, 0.f, 0.f);
#pragma unroll 8
        for (int d = kq * 32; d < kq * 32 + 32; d++)
            a = f4fma(t1[d], Q[d * 32 + jv], a);
        red[kq][jv] = a;
        __syncthreads();
        if (kq == 0) {
            float4 o = make_float4(0.f, 0.f, 0.f, 0.f);
#pragma unroll
            for (int q = 0; q < 8; q++) {
                float4 v = red[q][jv];
                o.x += v.x; o.y += v.y; o.z += v.z; o.w += v.w;
            }
            float ui = d_u[b * CI_ + i], pb = phi_b[i];
            float4 gb = ((const float4*)g_b)[jv];
            float4 vv = ((const float4*)(d_v + b * CI_))[jv];
            o.x += ui * gb.x + pb * vv.x + 65536.0f * pb * gb.x;
            o.y += ui * gb.y + pb * vv.y + 65536.0f * pb * gb.y;
            o.z += ui * gb.z + pb * vv.z + 65536.0f * pb * gb.z;
            o.w += ui * gb.w + pb * vv.w + 65536.0f * pb * gb.w;
            float* kt = d_kvT + (size_t)b * CI_ * CI_;
            kt[(jv * 4 + 0) * CI_ + i] = o.x;
            kt[(jv * 4 + 1) * CI_ + i] = o.y;
            kt[(jv * 4 + 2) * CI_ + i] = o.z;
            kt[(jv * 4 + 3) * CI_ + i] = o.w;
        }
    }
    gridbar();

    // ---------- phase 4: stageC+D fused (per m-row) ------------------------------
    if (bx < 256) {
        int m = bx;
        float*  ww   = (float*)shraw;
        float4 (*red)[32] = (float4 (*)[32])(shraw + 512);
        float*  mmv  = (float*)(shraw + 4608);
        float*  bred = (float*)(shraw + 5120);
        float4 (*redD)[64] = (float4 (*)[64])(shraw + 512);
        for (int b = 0; b < NB; b++) {
            if (t < CI_) ww[t] = W_w[m * CI_ + t];
            __syncthreads();
            int kq = t >> 5, iv = t & 31;
            const float4* Q = (const float4*)(d_kvT + (size_t)b * CI_ * CI_);
            float4 a = make_float4(0.f, 0.f, 0.f, 0.f);
#pragma unroll 8
            for (int j = kq * 16; j < kq * 16 + 16; j++)
                a = f4fma(ww[j], Q[j * 32 + iv], a);
            red[kq][iv] = a;
            __syncthreads();
            if (kq == 0) {
                float4 o = make_float4(0.f, 0.f, 0.f, 0.f);
#pragma unroll
                for (int q = 0; q < 8; q++) {
                    float4 v = red[q][iv];
                    o.x += v.x; o.y += v.y; o.z += v.z; o.w += v.w;
                }
                const float inv = 1.0f / 65536.0f;
                mmv[iv * 4 + 0] = o.x * inv;
                mmv[iv * 4 + 1] = o.y * inv;
                mmv[iv * 4 + 2] = o.z * inv;
                mmv[iv * 4 + 3] = o.w * inv;
            }
            __syncthreads();
            int kq2 = t >> 6, jv2 = t & 63;
            const float4* Qt = (const float4*)theta_w;
            float4 ad = make_float4(0.f, 0.f, 0.f, 0.f);
#pragma unroll 8
            for (int i = kq2 * 32; i < kq2 * 32 + 32; i++)
                ad = f4fma(mmv[i], Qt[i * 64 + jv2], ad);
            redD[kq2][jv2] = ad;
            if (t < CI_) bred[t] = mmv[t] * theta_b[t];
            __syncthreads();
            if (kq2 == 0) {
                float4 s0 = redD[0][jv2], s1 = redD[1][jv2], s2 = redD[2][jv2], s3 = redD[3][jv2];
                float a0 = s0.x + s1.x + s2.x + s3.x, a1 = s0.y + s1.y + s2.y + s3.y;
                float a2 = s0.z + s1.z + s2.z + s3.z, a3 = s0.w + s1.w + s2.w + s3.w;
                size_t base = ((size_t)b * C_ + m) * CI_ + jv2 * 2;
                d_Ah16[base]     = packh(a0, a1);
                d_Ah16[base + 1] = packh(a2, a3);
            }
            for (int s2v = 64; s2v > 0; s2v >>= 1) {
                if (t < s2v) bred[t] += bred[t + s2v];
                __syncthreads();
            }
            if (t == 0) d_b2[b * C_ + m] = bred[0] + W_b[m];
            __syncthreads();
        }
    }
}

// ================= pass 2: out = x + A x + b2 (cp.async X, occ 1) ================
// smem: A 64KB (sw512) | 3 X stages x 32KB (sw128) | b2 512B  (~161KB)
__global__ __launch_bounds__(256, 1) void pass2_kernel(const float* __restrict__ x,
                                                       float* __restrict__ out) {
    int start = blockIdx.x * TPC;
    int end = start + TPC; if (end > UNITS) end = UNITS;
    if (start >= UNITS) return;
    int nt = end - start;

    uint32_t ahb = smem_u32(dsm);
    uint32_t xsb = ahb + 65536u;
    float* b2s = (float*)(dsm + 65536 + 98304);

    int t = threadIdx.x, w = t >> 5, lane = t & 31;
    int m0 = (w >> 1) * 32;
    int n0w = (w & 1) * 32;

    auto loadX = [&](int u, int s) {
        int bg = u >> 11, n02 = (u & 1023) * NT2;
        const __half* src = d_xh + (size_t)bg * C_ * NNPOS + n02;
        uint32_t st = xsb + (uint32_t)s * 32768u;
#pragma unroll
        for (int i = 0; i < 8; i++) {
            int c = i * 256 + t;
            int row = c >> 3, col16 = c & 7;
            cpasync16(st + sw128((uint32_t)row * 128u + (uint32_t)col16 * 16u),
                      src + (size_t)row * NNPOS + col16 * 8);
        }
    };

    loadX(start, 0); CP_COMMIT();
    if (nt > 1) loadX(start + 1, 1);
    CP_COMMIT();

    int cur = -1;
    for (int it = 0; it < nt; it++) {
        int u = start + it;
        int bg = u >> 11, mh = (u >> 10) & 1, n0t = (u & 1023) * NT2;

        if ((u >> 10) != cur) {            // load A group (prev mma synced at loop end)
            const uint4* Ah4 = (const uint4*)(d_Ah16 + ((size_t)(bg * C_ + mh * 128)) * CI_);
#pragma unroll
            for (int ii = 0; ii < 16; ii++) {
                int idx = ii * 256 + t;
                uint32_t byte = (uint32_t)(idx >> 5) * 512u + (uint32_t)(idx & 31) * 16u;
                *(uint4*)(dsm + sw512(byte)) = Ah4[idx];
            }
            if (t < 128) b2s[t] = d_b2[bg * C_ + mh * 128 + t];
            cur = u >> 10;
            __syncthreads();
        }
        if (it + 2 < nt) loadX(u + 2, (it + 2) % 3);
        CP_COMMIT();
        CP_WAIT2();                        // X tile it resident
        __syncthreads();

        uint32_t xhb = xsb + (uint32_t)(it % 3) * 32768u;

        // residual prefetch (fp32 x) — LDG latency hides under the mma below
        size_t rb0[2];
        float2 rv0[2][4], rv1[2][4];
#pragma unroll
        for (int mt = 0; mt < 2; mt++) {
            int r = m0 + mt * 16 + (lane >> 2);
            rb0[mt] = ((size_t)(bg * C_ + mh * 128 + r)) * NNPOS + n0t + n0w + 2 * (lane & 3);
#pragma unroll
            for (int ntt = 0; ntt < 4; ntt++) {
                rv0[mt][ntt] = *(const float2*)(x + rb0[mt] + ntt * 8);
                rv1[mt][ntt] = *(const float2*)(x + rb0[mt] + (size_t)8 * NNPOS + ntt * 8);
            }
        }

        float acc[2][4][4];
#pragma unroll
        for (int i = 0; i < 2; i++)
#pragma unroll
            for (int j = 0; j < 4; j++)
#pragma unroll
                for (int q = 0; q < 4; q++) acc[i][j][q] = 0.f;

#pragma unroll 4
        for (int ks = 0; ks < 16; ks++) {
            int k0 = ks * 16;
            uint32_t ah[2][4];
#pragma unroll
            for (int mt = 0; mt < 2; mt++) {
                uint32_t byte = (uint32_t)(m0 + mt * 16 + (lane & 15)) * 512u
                              + (uint32_t)(k0 + (lane >> 4) * 8) * 2u;
                ldsm4(ah[mt], ahb + sw512(byte));
            }
            uint32_t bf[4][2];
            int g = lane >> 3, j = lane & 7;
#pragma unroll
            for (int n2 = 0; n2 < 2; n2++) {
                uint32_t rowk = (uint32_t)(k0 + (g & 1) * 8 + j);
                uint32_t coln = (uint32_t)(n0w + n2 * 16 + (g >> 1) * 8);
                uint32_t r[4];
                ldsm4t(r, xhb + sw128(rowk * 128u + coln * 2u));
                bf[n2 * 2][0] = r[0]; bf[n2 * 2][1] = r[1];
                bf[n2 * 2 + 1][0] = r[2]; bf[n2 * 2 + 1][1] = r[3];
            }
#pragma unroll
            for (int mt = 0; mt < 2; mt++)
#pragma unroll
                for (int nt2 = 0; nt2 < 4; nt2++)
                    mma16816h(acc[mt][nt2], ah[mt], bf[nt2]);
        }

        // epilogue: out = acc + x + b2 (fp32 residual from prefetched regs)
#pragma unroll
        for (int mt = 0; mt < 2; mt++) {
            int r = m0 + mt * 16 + (lane >> 2);
            float bv0 = b2s[r], bv1 = b2s[r + 8];
#pragma unroll
            for (int ntt = 0; ntt < 4; ntt++) {
                float2 o;
                o.x = acc[mt][ntt][0] + rv0[mt][ntt].x + bv0;
                o.y = acc[mt][ntt][1] + rv0[mt][ntt].y + bv0;
                *(float2*)(out + rb0[mt] + ntt * 8) = o;
                o.x = acc[mt][ntt][2] + rv1[mt][ntt].x + bv1;
                o.y = acc[mt][ntt][3] + rv1[mt][ntt].y + bv1;
                *(float2*)(out + rb0[mt] + (size_t)8 * NNPOS + ntt * 8) = o;
            }
        }
        __syncthreads();
    }
}

// ================= launch =================
extern "C" void kernel_launch(void* const* d_in, const int* in_sizes, int n_in,
                              void* d_out, int out_size) {
    const float* x       = (const float*)d_in[0];
    const float* g_w     = (const float*)d_in[1];
    const float* g_b     = (const float*)d_in[2];
    const float* theta_w = (const float*)d_in[3];
    const float* theta_b = (const float*)d_in[4];
    const float* phi_w   = (const float*)d_in[5];
    const float* phi_b   = (const float*)d_in[6];
    const float* W_w     = (const float*)d_in[7];
    const float* W_b     = (const float*)d_in[8];
    float* out = (float*)d_out;

    int smem1 = 3 * 32768;                  // 96KB, occ 2
    int smem2 = 65536 + 98304 + 1024;       // ~161KB, occ 1
    cudaFuncSetAttribute(pass1_kernel, cudaFuncAttributeMaxDynamicSharedMemorySize, smem1);
    cudaFuncSetAttribute(pass2_kernel, cudaFuncAttributeMaxDynamicSharedMemorySize, smem2);

    prepass_kernel<<<NB * C_, 256>>>(x);
    pass1_kernel<<<dim3(3, NCH1, NB), 256, smem1>>>();
    chain_kernel<<<CHAIN_BLOCKS, 256>>>(g_w, phi_w, g_b, phi_b, W_w, theta_w, theta_b, W_b);
    pass2_kernel<<<(UNITS + TPC - 1) / TPC, 256, smem2>>>(x, out);
}

// round 12
// speedup vs baseline: 5.2799x; 1.0023x over previous
#include <cuda_runtime.h>
#include <cuda_bf16.h>
#include <cuda_fp16.h>
#include <cstdint>
#include <cstddef>

#define NB 2
#define C_ 256
#define CI_ 128
#define NNPOS 65536
#define NCH1 49            // uneven k-chunks, pass1: 3 quads x 49 x 2 b = 294 CTAs
#define NT2 128            // spatial cols per pass2 tile
#define UNITS 2048         // NB * 2 mhalves * 512 ntiles
#define TPC 14             // units per CTA pass2 -> 147 CTAs (one wave)
#define CHAIN_BLOCKS 258

// ---------------- scratch (static device globals; no allocation) ----------------
__device__ __align__(16) __half   d_xh[(size_t)NB * C_ * NNPOS];       // x in fp16 (67MB)
__device__ __align__(16) float    d_Sp[(size_t)NB * NCH1 * 3 * 16384]; // partial S
__device__ __align__(16) float    d_S[NB * C_ * C_];
__device__ __align__(16) float    d_s[NB * C_];
__device__ __align__(16) float    d_gwT[C_ * CI_];        // g_w transposed [d][j]
__device__ __align__(16) float    d_T1[NB * CI_ * C_];
__device__ __align__(16) float    d_u[NB * CI_];
__device__ __align__(16) float    d_v[NB * CI_];
__device__ __align__(16) float    d_kvT[NB * CI_ * CI_];  // kv transposed [b][j][i]
__device__ __align__(16) float    d_b2[NB * C_];
__device__ __align__(16) uint32_t d_Ah16[NB * C_ * CI_];  // A fp16x2 [b][m][kpair]
__device__ unsigned d_cnt = 0;
__device__ unsigned d_gen = 0;

// ---------------- primitives ----------------
__device__ __forceinline__ uint32_t smem_u32(const void* p) {
    uint32_t a;
    asm("{ .reg .u64 t; cvta.to.shared.u64 t, %1; cvt.u32.u64 %0, t; }" : "=r"(a) : "l"(p));
    return a;
}
__device__ __forceinline__ void mma16816h(float* d, const uint32_t* a, const uint32_t* b) {
    asm volatile("mma.sync.aligned.m16n8k16.row.col.f32.f16.f16.f32 "
                 "{%0,%1,%2,%3}, {%4,%5,%6,%7}, {%8,%9}, {%0,%1,%2,%3};"
                 : "+f"(d[0]), "+f"(d[1]), "+f"(d[2]), "+f"(d[3])
                 : "r"(a[0]), "r"(a[1]), "r"(a[2]), "r"(a[3]), "r"(b[0]), "r"(b[1]));
}
__device__ __forceinline__ void ldsm4(uint32_t* r, uint32_t addr) {
    asm volatile("ldmatrix.sync.aligned.m8n8.x4.shared.b16 {%0,%1,%2,%3}, [%4];"
                 : "=r"(r[0]), "=r"(r[1]), "=r"(r[2]), "=r"(r[3]) : "r"(addr));
}
__device__ __forceinline__ void ldsm4t(uint32_t* r, uint32_t addr) {
    asm volatile("ldmatrix.sync.aligned.m8n8.x4.trans.shared.b16 {%0,%1,%2,%3}, [%4];"
                 : "=r"(r[0]), "=r"(r[1]), "=r"(r[2]), "=r"(r[3]) : "r"(addr));
}
__device__ __forceinline__ uint32_t sw128(uint32_t byte) { return byte ^ ((byte >> 3) & 0x70u); }
__device__ __forceinline__ uint32_t sw512(uint32_t byte) { return byte ^ ((byte >> 5) & 0x70u); }

__device__ __forceinline__ uint32_t packh(float x, float y) {
    __half2 h = __floats2half2_rn(x, y);
    return *(uint32_t*)&h;
}
__device__ __forceinline__ float4 f4fma(float s, float4 q, float4 a) {
    a.x += s * q.x; a.y += s * q.y; a.z += s * q.z; a.w += s * q.w;
    return a;
}
__device__ __forceinline__ void cpasync16(uint32_t dst, const void* src) {
    asm volatile("cp.async.cg.shared.global [%0], [%1], 16;" :: "r"(dst), "l"(src));
}
#define CP_COMMIT() asm volatile("cp.async.commit_group;" ::: "memory")
#define CP_WAIT1()  asm volatile("cp.async.wait_group 1;" ::: "memory")
#define CP_WAIT2()  asm volatile("cp.async.wait_group 2;" ::: "memory")

// grid-wide barrier (sense via monotonically increasing generation; replay-safe)
__device__ __forceinline__ void gridbar() {
    __syncthreads();
    if (threadIdx.x == 0) {
        __threadfence();
        unsigned g = *(volatile unsigned*)&d_gen;
        unsigned old = atomicAdd(&d_cnt, 1);
        if (old == CHAIN_BLOCKS - 1) {
            d_cnt = 0;
            __threadfence();
            atomicAdd(&d_gen, 1);
        } else {
            while (*(volatile unsigned*)&d_gen == g) { }
        }
        __threadfence();
    }
    __syncthreads();
}

extern __shared__ uint8_t dsm[];

// ================= prepass: x -> fp16 xh, rowsums =================
__global__ __launch_bounds__(256) void prepass_kernel(const float* __restrict__ x) {
    int row = blockIdx.x;                 // 0..511 = b*C_+c
    const float4* src = (const float4*)(x + (size_t)row * NNPOS);
    uint2* dst = (uint2*)(d_xh + (size_t)row * NNPOS);
    int t = threadIdx.x;
    float rs = 0.f;
#pragma unroll 4
    for (int i = t; i < NNPOS / 4; i += 256) {
        float4 v = src[i];
        rs += v.x + v.y + v.z + v.w;
        dst[i] = make_uint2(packh(v.x, v.y), packh(v.z, v.w));
    }
    __shared__ float red[256];
    red[t] = rs;
    __syncthreads();
    for (int s = 128; s > 0; s >>= 1) {
        if (t < s) red[t] += red[t + s];
        __syncthreads();
    }
    if (t == 0) d_s[row] = red[0];
}

// ================= pass 1: 3-quadrant syrk, cp.async 3-stage pipeline ============
// grid (3, NCH1, NB), block 256; smem = 3 stages x 32KB (A 16KB | B 16KB)
__global__ __launch_bounds__(256, 2) void pass1_kernel() {
    int qi = blockIdx.x, ch = blockIdx.y, b = blockIdx.z;
    int qm = qi >> 1, qn = (qi + 1) >> 1;   // 0:(0,0) 1:(0,1) 2:(1,1)
    bool diag = (qi != 1);
    int kt0 = (ch * 1024) / NCH1, kt1 = ((ch + 1) * 1024) / NCH1;
    const __half* xa = d_xh + ((size_t)(b * C_ + qm * 128)) * NNPOS;
    const __half* xb = d_xh + ((size_t)(b * C_ + qn * 128)) * NNPOS;

    int t = threadIdx.x, w = t >> 5, lane = t & 31;
    int wm = w >> 1, wn = w & 1;
    int m0 = wm * 32, n0 = wn * 64;
    uint32_t sbase = smem_u32(dsm);

    float acc[2][8][4];
#pragma unroll
    for (int i = 0; i < 2; i++)
#pragma unroll
        for (int j = 0; j < 8; j++)
#pragma unroll
            for (int q = 0; q < 4; q++) acc[i][j][q] = 0.f;

    auto load_tile = [&](int kt, int s) {
        uint32_t stA = sbase + (uint32_t)s * 32768u;
#pragma unroll
        for (int i = 0; i < 4; i++) {
            int c = i * 256 + t;
            int row = c >> 3, col16 = c & 7;
            cpasync16(stA + sw128((uint32_t)row * 128u + (uint32_t)col16 * 16u),
                      xa + (size_t)row * NNPOS + kt * 64 + col16 * 8);
        }
        if (!diag) {
            uint32_t stB = stA + 16384u;
#pragma unroll
            for (int i = 0; i < 4; i++) {
                int c = i * 256 + t;
                int row = c >> 3, col16 = c & 7;
                cpasync16(stB + sw128((uint32_t)row * 128u + (uint32_t)col16 * 16u),
                          xb + (size_t)row * NNPOS + kt * 64 + col16 * 8);
            }
        }
    };

    int nkt = kt1 - kt0;
    load_tile(kt0, 0); CP_COMMIT();
    if (nkt > 1) load_tile(kt0 + 1, 1);
    CP_COMMIT();

    for (int i = 0; i < nkt; i++) {
        if (i + 2 < nkt) load_tile(kt0 + i + 2, (i + 2) % 3);
        CP_COMMIT();                       // always one group per iter (may be empty)
        CP_WAIT2();                        // tile i resident
        __syncthreads();
        uint32_t ahb = sbase + (uint32_t)(i % 3) * 32768u;
        uint32_t bhb = diag ? ahb : ahb + 16384u;
#pragma unroll
        for (int ks = 0; ks < 4; ks++) {
            int k0 = ks * 16;
            uint32_t ah[2][4];
#pragma unroll
            for (int mt = 0; mt < 2; mt++) {
                uint32_t byte = (uint32_t)(m0 + mt * 16 + (lane & 15)) * 128u
                              + (uint32_t)(k0 + (lane >> 4) * 8) * 2u;
                ldsm4(ah[mt], ahb + sw128(byte));
            }
            uint32_t bf[8][2];
            int g = lane >> 3, j = lane & 7;
#pragma unroll
            for (int n2 = 0; n2 < 4; n2++) {
                uint32_t row = (uint32_t)(n0 + n2 * 16 + (g >> 1) * 8 + j);
                uint32_t kk  = (uint32_t)(k0 + (g & 1) * 8);
                uint32_t r[4];
                ldsm4(r, bhb + sw128(row * 128u + kk * 2u));
                bf[n2 * 2][0] = r[0]; bf[n2 * 2][1] = r[1];
                bf[n2 * 2 + 1][0] = r[2]; bf[n2 * 2 + 1][1] = r[3];
            }
#pragma unroll
            for (int mt = 0; mt < 2; mt++)
#pragma unroll
                for (int nt = 0; nt < 8; nt++)
                    mma16816h(acc[mt][nt], ah[mt], bf[nt]);
        }
        __syncthreads();
    }

    float* Sp = d_Sp + (((size_t)(b * NCH1 + ch) * 3 + qi) << 14);
#pragma unroll
    for (int mt = 0; mt < 2; mt++) {
        int r = m0 + mt * 16 + (lane >> 2);
        int c = n0 + 2 * (lane & 3);
#pragma unroll
        for (int nt = 0; nt < 8; nt++) {
            *(float2*)(Sp + (size_t)r * 128 + c + nt * 8)
                = make_float2(acc[mt][nt][0], acc[mt][nt][1]);
            *(float2*)(Sp + (size_t)(r + 8) * 128 + c + nt * 8)
                = make_float2(acc[mt][nt][2], acc[mt][nt][3]);
        }
    }
}

// ================= chain: reduce+mirror+gwt | stageA | stageB | stageC+D =========
__global__ __launch_bounds__(256, 2) void chain_kernel(
    const float* __restrict__ g_w, const float* __restrict__ phi_w,
    const float* __restrict__ g_b, const float* __restrict__ phi_b,
    const float* __restrict__ W_w, const float* __restrict__ theta_w,
    const float* __restrict__ theta_b, const float* __restrict__ W_b) {
    __shared__ __align__(16) uint8_t shraw[8448];
    int bx = blockIdx.x, t = threadIdx.x;

    // ---------- phase 1: reduce partial S (+mirror), gwt transpose ---------------
    if (bx < 96) {
        int id = bx * 256 + t;
        int b = id / 12288, rest = id % 12288;
        int slot = rest >> 12, idx4 = rest & 4095;
        const float4* p = (const float4*)d_Sp;
        size_t base = ((size_t)b * NCH1 * 3 + slot) * 4096 + idx4;
        float4 a = make_float4(0.f, 0.f, 0.f, 0.f);
#pragma unroll 7
        for (int ch = 0; ch < NCH1; ch++) {
            float4 v = p[base + (size_t)ch * 3 * 4096];
            a.x += v.x; a.y += v.y; a.z += v.z; a.w += v.w;
        }
        int ml = idx4 >> 5, c4 = idx4 & 31;
        int m = (slot == 2) ? 128 + ml : ml;
        int n4 = (slot == 0) ? c4 : 32 + c4;
        ((float4*)d_S)[(size_t)b * 16384 + m * 64 + n4] = a;
        if (slot == 1) {                       // mirror quad(1,0) = quad(0,1)^T
            float* Sb = d_S + (size_t)b * 65536;
            int nb = 128 + c4 * 4;
            Sb[(size_t)(nb + 0) * 256 + ml] = a.x;
            Sb[(size_t)(nb + 1) * 256 + ml] = a.y;
            Sb[(size_t)(nb + 2) * 256 + ml] = a.z;
            Sb[(size_t)(nb + 3) * 256 + ml] = a.w;
        }
    } else if (bx < 128) {                     // gwt: transpose g_w -> d_gwT
        float (*tile)[33] = (float (*)[33])shraw;
        int tb = bx - 96;
        int rt = tb >> 3, ct = tb & 7;
        int ty = t >> 5, tx = t & 31;
#pragma unroll
        for (int p = 0; p < 4; p++)
            tile[p * 8 + ty][tx] = g_w[(rt * 32 + p * 8 + ty) * C_ + ct * 32 + tx];
        __syncthreads();
#pragma unroll
        for (int p = 0; p < 4; p++)
            d_gwT[(ct * 32 + p * 8 + ty) * CI_ + rt * 32 + tx] = tile[tx][p * 8 + ty];
    }
    gridbar();

    // ---------- phase 2: stageA (T1 = phi_w @ S ; u,v) ---------------------------
    {
        int i = bx >> 1, b = bx & 1;
        if (i < CI_) {
            float* ph = (float*)shraw;
            float4 (*red)[64] = (float4 (*)[64])(shraw + 1024);
            ph[t] = phi_w[i * C_ + t];
            __syncthreads();
            int kq = t >> 6, jv = t & 63;
            const float4* S4 = (const float4*)(d_S + (size_t)b * 65536);
            float4 a = make_float4(0.f, 0.f, 0.f, 0.f);
#pragma unroll 8
            for (int c = kq * 64; c < kq * 64 + 64; c++)
                a = f4fma(ph[c], S4[c * 64 + jv], a);
            red[kq][jv] = a;
            __syncthreads();
            if (kq == 0) {
                float4 s0 = red[0][jv], s1 = red[1][jv], s2 = red[2][jv], s3 = red[3][jv];
                float4 o;
                o.x = s0.x + s1.x + s2.x + s3.x; o.y = s0.y + s1.y + s2.y + s3.y;
                o.z = s0.z + s1.z + s2.z + s3.z; o.w = s0.w + s1.w + s2.w + s3.w;
                ((float4*)(d_T1 + ((size_t)b * CI_ + i) * C_))[jv] = o;
            }
        } else if (i == CI_) {
            float* ss = (float*)shraw;
            ss[t] = d_s[b * C_ + t];
            __syncthreads();
            int hf = t >> 7, ii = t & 127;
            const float4* wr = (const float4*)((hf ? g_w : phi_w) + ii * C_);
            const float4* sv = (const float4*)ss;
            float acc = 0.f;
#pragma unroll 8
            for (int q = 0; q < 64; q++) {
                float4 wv = wr[q], s4 = sv[q];
                acc += wv.x * s4.x + wv.y * s4.y + wv.z * s4.z + wv.w * s4.w;
            }
            if (hf) d_v[b * CI_ + ii] = acc; else d_u[b * CI_ + ii] = acc;
        }
    }
    gridbar();

    // ---------- phase 3: stageB (kvT) --------------------------------------------
    if (bx < 256) {
        int i = bx >> 1, b = bx & 1;
        float* t1 = (float*)shraw;
        float4 (*red)[32] = (float4 (*)[32])(shraw + 1024);
        t1[t] = d_T1[((size_t)b * CI_ + i) * C_ + t];
        __syncthreads();
        int kq = t >> 5, jv = t & 31;
        const float4* Q = (const float4*)d_gwT;
        float4 a = make_float4(0.f, 0.f, 0.f, 0.f);
#pragma unroll 8
        for (int d = kq * 32; d < kq * 32 + 32; d++)
            a = f4fma(t1[d], Q[d * 32 + jv], a);
        red[kq][jv] = a;
        __syncthreads();
        if (kq == 0) {
            float4 o = make_float4(0.f, 0.f, 0.f, 0.f);
#pragma unroll
            for (int q = 0; q < 8; q++) {
                float4 v = red[q][jv];
                o.x += v.x; o.y += v.y; o.z += v.z; o.w += v.w;
            }
            float ui = d_u[b * CI_ + i], pb = phi_b[i];
            float4 gb = ((const float4*)g_b)[jv];
            float4 vv = ((const float4*)(d_v + b * CI_))[jv];
            o.x += ui * gb.x + pb * vv.x + 65536.0f * pb * gb.x;
            o.y += ui * gb.y + pb * vv.y + 65536.0f * pb * gb.y;
            o.z += ui * gb.z + pb * vv.z + 65536.0f * pb * gb.z;
            o.w += ui * gb.w + pb * vv.w + 65536.0f * pb * gb.w;
            float* kt = d_kvT + (size_t)b * CI_ * CI_;
            kt[(jv * 4 + 0) * CI_ + i] = o.x;
            kt[(jv * 4 + 1) * CI_ + i] = o.y;
            kt[(jv * 4 + 2) * CI_ + i] = o.z;
            kt[(jv * 4 + 3) * CI_ + i] = o.w;
        }
    }
    gridbar();

    // ---------- phase 4: stageC+D fused (per m-row) ------------------------------
    if (bx < 256) {
        int m = bx;
        float*  ww   = (float*)shraw;
        float4 (*red)[32] = (float4 (*)[32])(shraw + 512);
        float*  mmv  = (float*)(shraw + 4608);
        float*  bred = (float*)(shraw + 5120);
        float4 (*redD)[64] = (float4 (*)[64])(shraw + 512);
        for (int b = 0; b < NB; b++) {
            if (t < CI_) ww[t] = W_w[m * CI_ + t];
            __syncthreads();
            int kq = t >> 5, iv = t & 31;
            const float4* Q = (const float4*)(d_kvT + (size_t)b * CI_ * CI_);
            float4 a = make_float4(0.f, 0.f, 0.f, 0.f);
#pragma unroll 8
            for (int j = kq * 16; j < kq * 16 + 16; j++)
                a = f4fma(ww[j], Q[j * 32 + iv], a);
            red[kq][iv] = a;
            __syncthreads();
            if (kq == 0) {
                float4 o = make_float4(0.f, 0.f, 0.f, 0.f);
#pragma unroll
                for (int q = 0; q < 8; q++) {
                    float4 v = red[q][iv];
                    o.x += v.x; o.y += v.y; o.z += v.z; o.w += v.w;
                }
                const float inv = 1.0f / 65536.0f;
                mmv[iv * 4 + 0] = o.x * inv;
                mmv[iv * 4 + 1] = o.y * inv;
                mmv[iv * 4 + 2] = o.z * inv;
                mmv[iv * 4 + 3] = o.w * inv;
            }
            __syncthreads();
            int kq2 = t >> 6, jv2 = t & 63;
            const float4* Qt = (const float4*)theta_w;
            float4 ad = make_float4(0.f, 0.f, 0.f, 0.f);
#pragma unroll 8
            for (int i = kq2 * 32; i < kq2 * 32 + 32; i++)
                ad = f4fma(mmv[i], Qt[i * 64 + jv2], ad);
            redD[kq2][jv2] = ad;
            if (t < CI_) bred[t] = mmv[t] * theta_b[t];
            __syncthreads();
            if (kq2 == 0) {
                float4 s0 = redD[0][jv2], s1 = redD[1][jv2], s2 = redD[2][jv2], s3 = redD[3][jv2];
                float a0 = s0.x + s1.x + s2.x + s3.x, a1 = s0.y + s1.y + s2.y + s3.y;
                float a2 = s0.z + s1.z + s2.z + s3.z, a3 = s0.w + s1.w + s2.w + s3.w;
                size_t base = ((size_t)b * C_ + m) * CI_ + jv2 * 2;
                d_Ah16[base]     = packh(a0, a1);
                d_Ah16[base + 1] = packh(a2, a3);
            }
            for (int s2v = 64; s2v > 0; s2v >>= 1) {
                if (t < s2v) bred[t] += bred[t + s2v];
                __syncthreads();
            }
            if (t == 0) d_b2[b * C_ + m] = bred[0] + W_b[m];
            __syncthreads();
        }
    }
}

// ================= pass 2: out = x + A x + b2 (512 thr, 128-col tiles) ===========
// smem: A 64KB (sw512) | 2 X stages x 64KB (two 32KB 64-col halves) | b2 512B
__global__ __launch_bounds__(512, 1) void pass2_kernel(const float* __restrict__ x,
                                                       float* __restrict__ out) {
    int start = blockIdx.x * TPC;
    int end = start + TPC; if (end > UNITS) end = UNITS;
    if (start >= UNITS) return;
    int nt = end - start;

    uint32_t ahb = smem_u32(dsm);
    uint32_t xsb = ahb + 65536u;
    float* b2s = (float*)(dsm + 65536 + 131072);

    int t = threadIdx.x, w = t >> 5, lane = t & 31;
    int m0 = (w >> 2) * 32;            // 4 m-warps over 128 rows
    int n0w = (w & 3) * 32;            // 4 n-warps over 128 cols

    auto loadX = [&](int u, int s) {
        int bg = u >> 10, n02 = (u & 511) * NT2;
        const __half* src = d_xh + (size_t)bg * C_ * NNPOS + n02;
        uint32_t st = xsb + (uint32_t)s * 65536u;
#pragma unroll
        for (int i = 0; i < 8; i++) {
            int c = i * 512 + t;               // 4096 16B-chunks: 256 rows x 16
            int row = c >> 4, col16 = c & 15;
            uint32_t half = (uint32_t)(col16 >> 3);
            uint32_t c8 = (uint32_t)(col16 & 7);
            cpasync16(st + half * 32768u + sw128((uint32_t)row * 128u + c8 * 16u),
                      src + (size_t)row * NNPOS + col16 * 8);
        }
    };

    loadX(start, 0); CP_COMMIT();

    int cur = -1;
    for (int it = 0; it < nt; it++) {
        int u = start + it;
        int bg = u >> 10, mh = (u >> 9) & 1, n0t = (u & 511) * NT2;

        if ((u >> 9) != cur) {             // load A m-half (prev mma synced below)
            const uint4* Ah4 = (const uint4*)(d_Ah16 + ((size_t)(bg * C_ + mh * 128)) * CI_);
#pragma unroll
            for (int ii = 0; ii < 8; ii++) {
                int idx = ii * 512 + t;
                uint32_t byte = (uint32_t)(idx >> 5) * 512u + (uint32_t)(idx & 31) * 16u;
                *(uint4*)(dsm + sw512(byte)) = Ah4[idx];
            }
            if (t < 128) b2s[t] = d_b2[bg * C_ + mh * 128 + t];
            cur = u >> 9;
            __syncthreads();
        }
        if (it + 1 < nt) loadX(u + 1, (it + 1) & 1);
        CP_COMMIT();
        CP_WAIT1();                        // X tile it resident
        __syncthreads();

        uint32_t xhb = xsb + (uint32_t)(it & 1) * 65536u;

        float acc[2][4][4];
#pragma unroll
        for (int i = 0; i < 2; i++)
#pragma unroll
            for (int j = 0; j < 4; j++)
#pragma unroll
                for (int q = 0; q < 4; q++) acc[i][j][q] = 0.f;

#pragma unroll 4
        for (int ks = 0; ks < 16; ks++) {
            int k0 = ks * 16;
            uint32_t ah[2][4];
#pragma unroll
            for (int mt = 0; mt < 2; mt++) {
                uint32_t byte = (uint32_t)(m0 + mt * 16 + (lane & 15)) * 512u
                              + (uint32_t)(k0 + (lane >> 4) * 8) * 2u;
                ldsm4(ah[mt], ahb + sw512(byte));
            }
            uint32_t bf[4][2];
            int g = lane >> 3, j = lane & 7;
#pragma unroll
            for (int n2 = 0; n2 < 2; n2++) {
                uint32_t rowk = (uint32_t)(k0 + (g & 1) * 8 + j);
                uint32_t cg = (uint32_t)(n0w + n2 * 16 + (g >> 1) * 8);
                uint32_t half = cg >> 6, coln = cg & 63u;
                uint32_t r[4];
                ldsm4t(r, xhb + half * 32768u + sw128(rowk * 128u + coln * 2u));
                bf[n2 * 2][0] = r[0]; bf[n2 * 2][1] = r[1];
                bf[n2 * 2 + 1][0] = r[2]; bf[n2 * 2 + 1][1] = r[3];
            }
#pragma unroll
            for (int mt = 0; mt < 2; mt++)
#pragma unroll
                for (int nt2 = 0; nt2 < 4; nt2++)
                    mma16816h(acc[mt][nt2], ah[mt], bf[nt2]);
        }

        // epilogue: out = acc + x + b2 (fp32 residual; 16 warps amortize LDG latency)
#pragma unroll
        for (int mt = 0; mt < 2; mt++) {
            int r = m0 + mt * 16 + (lane >> 2);
            float bv0 = b2s[r], bv1 = b2s[r + 8];
            size_t base0 = ((size_t)(bg * C_ + mh * 128 + r)) * NNPOS + n0t + n0w + 2 * (lane & 3);
            size_t base1 = base0 + (size_t)8 * NNPOS;
#pragma unroll
            for (int ntt = 0; ntt < 4; ntt++) {
                float2 xv = *(const float2*)(x + base0 + ntt * 8);
                float2 o;
                o.x = acc[mt][ntt][0] + xv.x + bv0;
                o.y = acc[mt][ntt][1] + xv.y + bv0;
                *(float2*)(out + base0 + ntt * 8) = o;
                xv = *(const float2*)(x + base1 + ntt * 8);
                o.x = acc[mt][ntt][2] + xv.x + bv1;
                o.y = acc[mt][ntt][3] + xv.y + bv1;
                *(float2*)(out + base1 + ntt * 8) = o;
            }
        }
        __syncthreads();
    }
}

// ================= launch =================
extern "C" void kernel_launch(void* const* d_in, const int* in_sizes, int n_in,
                              void* d_out, int out_size) {
    const float* x       = (const float*)d_in[0];
    const float* g_w     = (const float*)d_in[1];
    const float* g_b     = (const float*)d_in[2];
    const float* theta_w = (const float*)d_in[3];
    const float* theta_b = (const float*)d_in[4];
    const float* phi_w   = (const float*)d_in[5];
    const float* phi_b   = (const float*)d_in[6];
    const float* W_w     = (const float*)d_in[7];
    const float* W_b     = (const float*)d_in[8];
    float* out = (float*)d_out;

    int smem1 = 3 * 32768;                  // 96KB, occ 2
    int smem2 = 65536 + 131072 + 1024;      // ~193KB, occ 1 (16 warps)
    cudaFuncSetAttribute(pass1_kernel, cudaFuncAttributeMaxDynamicSharedMemorySize, smem1);
    cudaFuncSetAttribute(pass2_kernel, cudaFuncAttributeMaxDynamicSharedMemorySize, smem2);

    prepass_kernel<<<NB * C_, 256>>>(x);
    pass1_kernel<<<dim3(3, NCH1, NB), 256, smem1>>>();
    chain_kernel<<<CHAIN_BLOCKS, 256>>>(g_w, phi_w, g_b, phi_b, W_w, theta_w, theta_b, W_b);
    pass2_kernel<<<(UNITS + TPC - 1) / TPC, 512, smem2>>>(x, out);
}